// round 11
// baseline (speedup 1.0000x reference)
#include <cuda_runtime.h>
#include <cuda_fp16.h>

#define N_NODES  50000
#define N_EDGES  1600000
#define N_GRAPHS 1000

// ---------------- scratch (device globals; no allocation allowed) ----------
__device__ __align__(16) float  g_x8[N_NODES * 8];      // padded node features (fp32)
__device__ __align__(16) __half g_x8h[N_NODES * 8];     // padded node features (fp16)
__device__ __align__(16) __half g_aggr1h[N_NODES * 8];  // layer1 aggregation (fp16 atomics)
__device__ __align__(16) float  g_h1[N_NODES * 64];     // layer1 output (fp32)
__device__ __align__(16) __half g_h1h[N_NODES * 64];    // layer1 output (fp16 gather copy)
__device__ __align__(16) __half g_aggr2h[N_NODES * 64]; // layer2 aggregation (fp16 atomics)
__device__ __align__(16) float  g_sums[N_GRAPHS * 64];  // pooled sums
__device__ __align__(16) float  g_cnt[N_GRAPHS];        // per-graph node counts

// ---------------- zero scratch + pad x ---------------------------------------
#define ZX  (N_NODES * 2)
#define ZA2 (ZX + N_NODES * 8)
#define ZSM (ZA2 + N_GRAPHS * 16)
__global__ void zero_kernel(const float* __restrict__ x) {
    int i = blockIdx.x * blockDim.x + threadIdx.x;
    if (i < ZX) {
        int node = i >> 1, h = i & 1;
        int base = node * 7 + h * 4;
        float4 v;
        v.x = __ldg(&x[base + 0]);
        v.y = __ldg(&x[base + 1]);
        v.z = __ldg(&x[base + 2]);
        v.w = (h == 0) ? __ldg(&x[base + 3]) : 0.f;   // j=7 pad
        reinterpret_cast<float4*>(g_x8)[i] = v;
        __half2 p0 = __floats2half2_rn(v.x, v.y);
        __half2 p1 = __floats2half2_rn(v.z, v.w);
        uint2 u;
        u.x = *reinterpret_cast<unsigned*>(&p0);
        u.y = *reinterpret_cast<unsigned*>(&p1);
        *reinterpret_cast<uint2*>(reinterpret_cast<char*>(g_x8h) + node * 16 + h * 8) = u;
        if (i < N_NODES)
            reinterpret_cast<uint4*>(g_aggr1h)[i] = make_uint4(0, 0, 0, 0);
    } else if (i < ZA2) {
        reinterpret_cast<uint4*>(g_aggr2h)[i - ZX] = make_uint4(0, 0, 0, 0);
    } else if (i < ZSM) {
        reinterpret_cast<float4*>(g_sums)[i - ZA2] = make_float4(0.f, 0.f, 0.f, 0.f);
    }
    if (i < N_GRAPHS) g_cnt[i] = 0.f;
}

// ---------------- layer 1 edge pass (d = 7): ONE v4.f16x2 red per edge ------
__global__ void edge1_kernel(const float* __restrict__ ea,
                             const int*   __restrict__ ei,
                             const float* __restrict__ We1,
                             const float* __restrict__ be1) {
    float w[4][7], b[7];
#pragma unroll
    for (int i = 0; i < 4; i++)
#pragma unroll
        for (int j = 0; j < 7; j++)
            w[i][j] = __ldg(&We1[i * 7 + j]);
#pragma unroll
    for (int j = 0; j < 7; j++) b[j] = __ldg(&be1[j]);

    int t  = blockIdx.x * blockDim.x + threadIdx.x;
    int nt = gridDim.x * blockDim.x;
    for (int e = t; e < N_EDGES; e += nt) {
        int src = __ldg(&ei[e]);
        int dst = __ldg(&ei[N_EDGES + e]);
        float4 a = __ldg(reinterpret_cast<const float4*>(ea) + e);
        uint4 xh = __ldg(reinterpret_cast<const uint4*>(g_x8h) + src);
        float2 x01 = __half22float2(*reinterpret_cast<__half2*>(&xh.x));
        float2 x23 = __half22float2(*reinterpret_cast<__half2*>(&xh.y));
        float2 x45 = __half22float2(*reinterpret_cast<__half2*>(&xh.z));
        float2 x67 = __half22float2(*reinterpret_cast<__half2*>(&xh.w));
        float xs[8] = {x01.x, x01.y, x23.x, x23.y, x45.x, x45.y, x67.x, 0.f};
        float v[8];
#pragma unroll
        for (int j = 0; j < 7; j++) {
            float m = b[j] + a.x * w[0][j] + a.y * w[1][j]
                            + a.z * w[2][j] + a.w * w[3][j];
            v[j] = fmaxf(m + xs[j], 0.f);
        }
        v[7] = 0.f;
        __half2 p0 = __floats2half2_rn(v[0], v[1]);
        __half2 p1 = __floats2half2_rn(v[2], v[3]);
        __half2 p2 = __floats2half2_rn(v[4], v[5]);
        __half2 p3 = __floats2half2_rn(v[6], v[7]);
        __half* p = g_aggr1h + dst * 8;
        asm volatile("red.global.add.noftz.v4.f16x2 [%0], {%1, %2, %3, %4};"
                     :: "l"(p),
                        "r"(*reinterpret_cast<unsigned*>(&p0)),
                        "r"(*reinterpret_cast<unsigned*>(&p1)),
                        "r"(*reinterpret_cast<unsigned*>(&p2)),
                        "r"(*reinterpret_cast<unsigned*>(&p3)) : "memory");
    }
}

// ---------------- layer 1 node MLP: 7 -> 64 -> 64, 4-node blocked ----------
#define N_GROUPS (N_NODES / 4)
__global__ void node1_kernel(const float* __restrict__ W1a,
                             const float* __restrict__ b1a,
                             const float* __restrict__ W1b,
                             const float* __restrict__ b1b) {
    __shared__ float2 sWa[7 * 32];
    __shared__ float2 sWb[64 * 32];
    __shared__ float  sba[64];
    __shared__ float  sbb[64];
    for (int i = threadIdx.x; i < 7 * 32; i += blockDim.x)
        sWa[i] = reinterpret_cast<const float2*>(W1a)[i];
    for (int i = threadIdx.x; i < 64 * 32; i += blockDim.x)
        sWb[i] = reinterpret_cast<const float2*>(W1b)[i];
    if (threadIdx.x < 64) { sba[threadIdx.x] = b1a[threadIdx.x]; sbb[threadIdx.x] = b1b[threadIdx.x]; }
    __syncthreads();

    int warp = (blockIdx.x * blockDim.x + threadIdx.x) >> 5;
    int nw   = (gridDim.x * blockDim.x) >> 5;
    int lane = threadIdx.x & 31;
    int j    = lane * 2;

    for (int grp = warp; grp < N_GROUPS; grp += nw) {
        int n0 = grp * 4;
        float z[4][7];
#pragma unroll
        for (int m = 0; m < 4; m++) {
            uint4 ah = *reinterpret_cast<const uint4*>(g_aggr1h + (n0 + m) * 8);
            float2 a01 = __half22float2(*reinterpret_cast<__half2*>(&ah.x));
            float2 a23 = __half22float2(*reinterpret_cast<__half2*>(&ah.y));
            float2 a45 = __half22float2(*reinterpret_cast<__half2*>(&ah.z));
            float2 a67 = __half22float2(*reinterpret_cast<__half2*>(&ah.w));
            float as[7] = {a01.x, a01.y, a23.x, a23.y, a45.x, a45.y, a67.x};
#pragma unroll
            for (int k = 0; k < 7; k++)
                z[m][k] = g_x8[(n0 + m) * 8 + k] + as[k];
        }

        float t0[4], t1[4];
#pragma unroll
        for (int m = 0; m < 4; m++) { t0[m] = sba[j]; t1[m] = sba[j + 1]; }
#pragma unroll
        for (int k = 0; k < 7; k++) {
            float2 w = sWa[k * 32 + lane];
#pragma unroll
            for (int m = 0; m < 4; m++) {
                t0[m] += z[m][k] * w.x;
                t1[m] += z[m][k] * w.y;
            }
        }
#pragma unroll
        for (int m = 0; m < 4; m++) { t0[m] = fmaxf(t0[m], 0.f); t1[m] = fmaxf(t1[m], 0.f); }

        float a0[4], a1[4];
#pragma unroll
        for (int m = 0; m < 4; m++) { a0[m] = sbb[j]; a1[m] = sbb[j + 1]; }
#pragma unroll
        for (int k = 0; k < 64; k++) {
            float2 w = sWb[k * 32 + lane];
#pragma unroll
            for (int m = 0; m < 4; m++) {
                float tk = __shfl_sync(0xffffffffu, (k & 1) ? t1[m] : t0[m], k >> 1);
                a0[m] += tk * w.x;
                a1[m] += tk * w.y;
            }
        }
#pragma unroll
        for (int m = 0; m < 4; m++) {
            float v0 = fmaxf(a0[m], 0.f);   // outer relu from reference
            float v1 = fmaxf(a1[m], 0.f);
            *reinterpret_cast<float2*>(g_h1 + (n0 + m) * 64 + j) = make_float2(v0, v1);
            *reinterpret_cast<__half2*>(g_h1h + (n0 + m) * 64 + j) =
                __floats2half2_rn(v0, v1);
        }
    }
}

// ---------------- layer 2 edge pass (d = 64): 8 lanes per edge --------------
// lane owns output cols 8l..8l+7; weights in regs; loads for the edge PAIR
// issued up front (MLP), then edges retired one at a time (short live ranges).
// __launch_bounds__(256,3): cap 85 regs -> 37.5% occupancy.
#define E2_EPW 8
__global__ void __launch_bounds__(256, 3)
edge2_kernel(const float* __restrict__ ea,
             const int*   __restrict__ ei,
             const float* __restrict__ We2,
             const float* __restrict__ be2) {
    int l    = threadIdx.x & 7;                        // output slice 8l..8l+7
    int grp  = (blockIdx.x * blockDim.x + threadIdx.x) >> 3;
    int base = grp * E2_EPW;

    // per-lane weights: rows 0..3, cols 8l..8l+7 (two float4 per row) + bias
    float4 wa[4], wb[4];
#pragma unroll
    for (int r = 0; r < 4; r++) {
        wa[r] = __ldg(reinterpret_cast<const float4*>(We2 + r * 64) + 2 * l);
        wb[r] = __ldg(reinterpret_cast<const float4*>(We2 + r * 64) + 2 * l + 1);
    }
    float4 ba = __ldg(reinterpret_cast<const float4*>(be2) + 2 * l);
    float4 bc = __ldg(reinterpret_cast<const float4*>(be2) + 2 * l + 1);

#pragma unroll
    for (int i = 0; i < E2_EPW; i += 2) {
        int e0 = base + i;
        // issue all loads for the pair (2-deep gather MLP)
        int2 s01 = __ldg(reinterpret_cast<const int2*>(ei + e0));
        int2 d01 = __ldg(reinterpret_cast<const int2*>(ei + N_EDGES + e0));
        float4 a0 = __ldg(reinterpret_cast<const float4*>(ea) + e0);
        float4 a1 = __ldg(reinterpret_cast<const float4*>(ea) + e0 + 1);
        uint4 hg0 = __ldg(reinterpret_cast<const uint4*>(g_h1h + s01.x * 64) + l);
        uint4 hg1 = __ldg(reinterpret_cast<const uint4*>(g_h1h + s01.y * 64) + l);

        // retire edge 0 completely (frees its registers)
        {
            float2 h0 = __half22float2(*reinterpret_cast<__half2*>(&hg0.x));
            float2 h1 = __half22float2(*reinterpret_cast<__half2*>(&hg0.y));
            float2 h2 = __half22float2(*reinterpret_cast<__half2*>(&hg0.z));
            float2 h3 = __half22float2(*reinterpret_cast<__half2*>(&hg0.w));
            __half2 p0 = __floats2half2_rn(
                fmaxf(ba.x + a0.x*wa[0].x + a0.y*wa[1].x + a0.z*wa[2].x + a0.w*wa[3].x + h0.x, 0.f),
                fmaxf(ba.y + a0.x*wa[0].y + a0.y*wa[1].y + a0.z*wa[2].y + a0.w*wa[3].y + h0.y, 0.f));
            __half2 p1 = __floats2half2_rn(
                fmaxf(ba.z + a0.x*wa[0].z + a0.y*wa[1].z + a0.z*wa[2].z + a0.w*wa[3].z + h1.x, 0.f),
                fmaxf(ba.w + a0.x*wa[0].w + a0.y*wa[1].w + a0.z*wa[2].w + a0.w*wa[3].w + h1.y, 0.f));
            __half2 p2 = __floats2half2_rn(
                fmaxf(bc.x + a0.x*wb[0].x + a0.y*wb[1].x + a0.z*wb[2].x + a0.w*wb[3].x + h2.x, 0.f),
                fmaxf(bc.y + a0.x*wb[0].y + a0.y*wb[1].y + a0.z*wb[2].y + a0.w*wb[3].y + h2.y, 0.f));
            __half2 p3 = __floats2half2_rn(
                fmaxf(bc.z + a0.x*wb[0].z + a0.y*wb[1].z + a0.z*wb[2].z + a0.w*wb[3].z + h3.x, 0.f),
                fmaxf(bc.w + a0.x*wb[0].w + a0.y*wb[1].w + a0.z*wb[2].w + a0.w*wb[3].w + h3.y, 0.f));
            __half* p = g_aggr2h + d01.x * 64 + l * 8;
            asm volatile("red.global.add.noftz.v4.f16x2 [%0], {%1, %2, %3, %4};"
                         :: "l"(p),
                            "r"(*reinterpret_cast<unsigned*>(&p0)),
                            "r"(*reinterpret_cast<unsigned*>(&p1)),
                            "r"(*reinterpret_cast<unsigned*>(&p2)),
                            "r"(*reinterpret_cast<unsigned*>(&p3)) : "memory");
        }
        // retire edge 1
        {
            float2 h0 = __half22float2(*reinterpret_cast<__half2*>(&hg1.x));
            float2 h1 = __half22float2(*reinterpret_cast<__half2*>(&hg1.y));
            float2 h2 = __half22float2(*reinterpret_cast<__half2*>(&hg1.z));
            float2 h3 = __half22float2(*reinterpret_cast<__half2*>(&hg1.w));
            __half2 p0 = __floats2half2_rn(
                fmaxf(ba.x + a1.x*wa[0].x + a1.y*wa[1].x + a1.z*wa[2].x + a1.w*wa[3].x + h0.x, 0.f),
                fmaxf(ba.y + a1.x*wa[0].y + a1.y*wa[1].y + a1.z*wa[2].y + a1.w*wa[3].y + h0.y, 0.f));
            __half2 p1 = __floats2half2_rn(
                fmaxf(ba.z + a1.x*wa[0].z + a1.y*wa[1].z + a1.z*wa[2].z + a1.w*wa[3].z + h1.x, 0.f),
                fmaxf(ba.w + a1.x*wa[0].w + a1.y*wa[1].w + a1.z*wa[2].w + a1.w*wa[3].w + h1.y, 0.f));
            __half2 p2 = __floats2half2_rn(
                fmaxf(bc.x + a1.x*wb[0].x + a1.y*wb[1].x + a1.z*wb[2].x + a1.w*wb[3].x + h2.x, 0.f),
                fmaxf(bc.y + a1.x*wb[0].y + a1.y*wb[1].y + a1.z*wb[2].y + a1.w*wb[3].y + h2.y, 0.f));
            __half2 p3 = __floats2half2_rn(
                fmaxf(bc.z + a1.x*wb[0].z + a1.y*wb[1].z + a1.z*wb[2].z + a1.w*wb[3].z + h3.x, 0.f),
                fmaxf(bc.w + a1.x*wb[0].w + a1.y*wb[1].w + a1.z*wb[2].w + a1.w*wb[3].w + h3.y, 0.f));
            __half* p = g_aggr2h + d01.y * 64 + l * 8;
            asm volatile("red.global.add.noftz.v4.f16x2 [%0], {%1, %2, %3, %4};"
                         :: "l"(p),
                            "r"(*reinterpret_cast<unsigned*>(&p0)),
                            "r"(*reinterpret_cast<unsigned*>(&p1)),
                            "r"(*reinterpret_cast<unsigned*>(&p2)),
                            "r"(*reinterpret_cast<unsigned*>(&p3)) : "memory");
        }
    }
}

// ---------------- layer 2 node MLP (64->64->64) + pool, 4-node blocked -----
__global__ void node2pool_kernel(const int*   __restrict__ batch,
                                 const float* __restrict__ W2a,
                                 const float* __restrict__ b2a,
                                 const float* __restrict__ W2b,
                                 const float* __restrict__ b2b) {
    __shared__ float2 sWa[64 * 32];
    __shared__ float2 sWb[64 * 32];
    __shared__ float  sba[64];
    __shared__ float  sbb[64];
    for (int i = threadIdx.x; i < 64 * 32; i += blockDim.x) {
        sWa[i] = reinterpret_cast<const float2*>(W2a)[i];
        sWb[i] = reinterpret_cast<const float2*>(W2b)[i];
    }
    if (threadIdx.x < 64) { sba[threadIdx.x] = b2a[threadIdx.x]; sbb[threadIdx.x] = b2b[threadIdx.x]; }
    __syncthreads();

    int warp = (blockIdx.x * blockDim.x + threadIdx.x) >> 5;
    int nw   = (gridDim.x * blockDim.x) >> 5;
    int lane = threadIdx.x & 31;
    int j    = lane * 2;

    for (int grp = warp; grp < N_GROUPS; grp += nw) {
        int n0 = grp * 4;
        float z0[4], z1[4];
#pragma unroll
        for (int m = 0; m < 4; m++) {
            float2 hv = *reinterpret_cast<const float2*>(g_h1 + (n0 + m) * 64 + j);
            float2 av = __half22float2(
                *reinterpret_cast<const __half2*>(g_aggr2h + (n0 + m) * 64 + j));
            z0[m] = hv.x + av.x;
            z1[m] = hv.y + av.y;
        }

        float t0[4], t1[4];
#pragma unroll
        for (int m = 0; m < 4; m++) { t0[m] = sba[j]; t1[m] = sba[j + 1]; }
#pragma unroll
        for (int k = 0; k < 64; k++) {
            float2 w = sWa[k * 32 + lane];
#pragma unroll
            for (int m = 0; m < 4; m++) {
                float zk = __shfl_sync(0xffffffffu, (k & 1) ? z1[m] : z0[m], k >> 1);
                t0[m] += zk * w.x;
                t1[m] += zk * w.y;
            }
        }
#pragma unroll
        for (int m = 0; m < 4; m++) { t0[m] = fmaxf(t0[m], 0.f); t1[m] = fmaxf(t1[m], 0.f); }

        float a0[4], a1[4];
#pragma unroll
        for (int m = 0; m < 4; m++) { a0[m] = sbb[j]; a1[m] = sbb[j + 1]; }
#pragma unroll
        for (int k = 0; k < 64; k++) {
            float2 w = sWb[k * 32 + lane];
#pragma unroll
            for (int m = 0; m < 4; m++) {
                float tk = __shfl_sync(0xffffffffu, (k & 1) ? t1[m] : t0[m], k >> 1);
                a0[m] += tk * w.x;
                a1[m] += tk * w.y;
            }
        }
#pragma unroll
        for (int m = 0; m < 4; m++) {
            float v0 = fmaxf(a0[m], 0.f);   // outer relu from reference
            float v1 = fmaxf(a1[m], 0.f);
            int g = batch[n0 + m];
            float* p = g_sums + g * 64 + j;
            asm volatile("red.global.add.v2.f32 [%0], {%1, %2};"
                         :: "l"(p), "f"(v0), "f"(v1) : "memory");
            if (lane == 0) atomicAdd(&g_cnt[g], 1.0f);
        }
    }
}

// ---------------- final FC: pooled[G,64] @ Wfc[64,12] + bfc -----------------
__global__ void fc_kernel(const float* __restrict__ Wfc,
                          const float* __restrict__ bfc,
                          float* __restrict__ out) {
    int i = blockIdx.x * blockDim.x + threadIdx.x;
    if (i >= N_GRAPHS * 12) return;
    int g = i / 12;
    int c = i % 12;
    float inv = 1.0f / fmaxf(g_cnt[g], 1.0f);
    float acc = 0.f;
#pragma unroll
    for (int k = 0; k < 64; k++)
        acc += g_sums[g * 64 + k] * Wfc[k * 12 + c];
    out[i] = bfc[c] + inv * acc;
}

// ---------------- launch ----------------------------------------------------
extern "C" void kernel_launch(void* const* d_in, const int* in_sizes, int n_in,
                              void* d_out, int out_size) {
    const float* x    = (const float*)d_in[0];
    const float* ea   = (const float*)d_in[1];
    const int*   ei   = (const int*)  d_in[2];
    const int*   batch= (const int*)  d_in[3];
    const float* We1  = (const float*)d_in[4];
    const float* be1  = (const float*)d_in[5];
    const float* W1a  = (const float*)d_in[6];
    const float* b1a  = (const float*)d_in[7];
    const float* W1b  = (const float*)d_in[8];
    const float* b1b  = (const float*)d_in[9];
    const float* We2  = (const float*)d_in[10];
    const float* be2  = (const float*)d_in[11];
    const float* W2a  = (const float*)d_in[12];
    const float* b2a  = (const float*)d_in[13];
    const float* W2b  = (const float*)d_in[14];
    const float* b2b  = (const float*)d_in[15];
    const float* Wfc  = (const float*)d_in[16];
    const float* bfc  = (const float*)d_in[17];
    float* out = (float*)d_out;

    zero_kernel<<<(ZSM + 255) / 256, 256>>>(x);
    edge1_kernel<<<1184, 256>>>(ea, ei, We1, be1);
    node1_kernel<<<592, 256>>>(W1a, b1a, W1b, b1b);
    edge2_kernel<<<(N_EDGES / E2_EPW) * 8 / 256, 256>>>(ea, ei, We2, be2);
    node2pool_kernel<<<592, 256>>>(batch, W2a, b2a, W2b, b2b);
    fc_kernel<<<(N_GRAPHS * 12 + 255) / 256, 256>>>(Wfc, bfc, out);
}

// round 12
// speedup vs baseline: 1.1172x; 1.1172x over previous
#include <cuda_runtime.h>
#include <cuda_fp16.h>

#define N_NODES  50000
#define N_EDGES  1600000
#define N_GRAPHS 1000

// ---------------- scratch (device globals; no allocation allowed) ----------
__device__ __align__(16) float  g_x8[N_NODES * 8];      // padded node features (fp32)
__device__ __align__(16) __half g_x8h[N_NODES * 8];     // padded node features (fp16)
__device__ __align__(16) __half g_aggr1h[N_NODES * 8];  // layer1 aggregation (fp16 atomics)
__device__ __align__(16) float  g_h1[N_NODES * 64];     // layer1 output (fp32)
__device__ __align__(16) __half g_h1h[N_NODES * 64];    // layer1 output (fp16 gather copy)
__device__ __align__(16) __half g_aggr2h[N_NODES * 64]; // layer2 aggregation (fp16 atomics)
__device__ __align__(16) float  g_sums[N_GRAPHS * 64];  // pooled sums
__device__ __align__(16) float  g_cnt[N_GRAPHS];        // per-graph node counts

// ---------------- zero scratch + pad x ---------------------------------------
#define ZX  (N_NODES * 2)
#define ZA2 (ZX + N_NODES * 8)
#define ZSM (ZA2 + N_GRAPHS * 16)
__global__ void zero_kernel(const float* __restrict__ x) {
    int i = blockIdx.x * blockDim.x + threadIdx.x;
    if (i < ZX) {
        int node = i >> 1, h = i & 1;
        int base = node * 7 + h * 4;
        float4 v;
        v.x = __ldg(&x[base + 0]);
        v.y = __ldg(&x[base + 1]);
        v.z = __ldg(&x[base + 2]);
        v.w = (h == 0) ? __ldg(&x[base + 3]) : 0.f;   // j=7 pad
        reinterpret_cast<float4*>(g_x8)[i] = v;
        __half2 p0 = __floats2half2_rn(v.x, v.y);
        __half2 p1 = __floats2half2_rn(v.z, v.w);
        uint2 u;
        u.x = *reinterpret_cast<unsigned*>(&p0);
        u.y = *reinterpret_cast<unsigned*>(&p1);
        *reinterpret_cast<uint2*>(reinterpret_cast<char*>(g_x8h) + node * 16 + h * 8) = u;
        if (i < N_NODES)
            reinterpret_cast<uint4*>(g_aggr1h)[i] = make_uint4(0, 0, 0, 0);
    } else if (i < ZA2) {
        reinterpret_cast<uint4*>(g_aggr2h)[i - ZX] = make_uint4(0, 0, 0, 0);
    } else if (i < ZSM) {
        reinterpret_cast<float4*>(g_sums)[i - ZA2] = make_float4(0.f, 0.f, 0.f, 0.f);
    }
    if (i < N_GRAPHS) g_cnt[i] = 0.f;
}

// ---------------- layer 1 edge pass (d = 7): ONE v4.f16x2 red per edge ------
__global__ void edge1_kernel(const float* __restrict__ ea,
                             const int*   __restrict__ ei,
                             const float* __restrict__ We1,
                             const float* __restrict__ be1) {
    float w[4][7], b[7];
#pragma unroll
    for (int i = 0; i < 4; i++)
#pragma unroll
        for (int j = 0; j < 7; j++)
            w[i][j] = __ldg(&We1[i * 7 + j]);
#pragma unroll
    for (int j = 0; j < 7; j++) b[j] = __ldg(&be1[j]);

    int t  = blockIdx.x * blockDim.x + threadIdx.x;
    int nt = gridDim.x * blockDim.x;
    for (int e = t; e < N_EDGES; e += nt) {
        int src = __ldg(&ei[e]);
        int dst = __ldg(&ei[N_EDGES + e]);
        float4 a = __ldg(reinterpret_cast<const float4*>(ea) + e);
        uint4 xh = __ldg(reinterpret_cast<const uint4*>(g_x8h) + src);
        float2 x01 = __half22float2(*reinterpret_cast<__half2*>(&xh.x));
        float2 x23 = __half22float2(*reinterpret_cast<__half2*>(&xh.y));
        float2 x45 = __half22float2(*reinterpret_cast<__half2*>(&xh.z));
        float2 x67 = __half22float2(*reinterpret_cast<__half2*>(&xh.w));
        float xs[8] = {x01.x, x01.y, x23.x, x23.y, x45.x, x45.y, x67.x, 0.f};
        float v[8];
#pragma unroll
        for (int j = 0; j < 7; j++) {
            float m = b[j] + a.x * w[0][j] + a.y * w[1][j]
                            + a.z * w[2][j] + a.w * w[3][j];
            v[j] = fmaxf(m + xs[j], 0.f);
        }
        v[7] = 0.f;
        __half2 p0 = __floats2half2_rn(v[0], v[1]);
        __half2 p1 = __floats2half2_rn(v[2], v[3]);
        __half2 p2 = __floats2half2_rn(v[4], v[5]);
        __half2 p3 = __floats2half2_rn(v[6], v[7]);
        __half* p = g_aggr1h + dst * 8;
        asm volatile("red.global.add.noftz.v4.f16x2 [%0], {%1, %2, %3, %4};"
                     :: "l"(p),
                        "r"(*reinterpret_cast<unsigned*>(&p0)),
                        "r"(*reinterpret_cast<unsigned*>(&p1)),
                        "r"(*reinterpret_cast<unsigned*>(&p2)),
                        "r"(*reinterpret_cast<unsigned*>(&p3)) : "memory");
    }
}

// ---------------- layer 1 node MLP: 7 -> 64 -> 64, 8-node blocked ----------
#define N_GROUPS (N_NODES / 8)
__global__ void node1_kernel(const float* __restrict__ W1a,
                             const float* __restrict__ b1a,
                             const float* __restrict__ W1b,
                             const float* __restrict__ b1b) {
    __shared__ float2 sWa[7 * 32];
    __shared__ float2 sWb[64 * 32];
    __shared__ float  sba[64];
    __shared__ float  sbb[64];
    for (int i = threadIdx.x; i < 7 * 32; i += blockDim.x)
        sWa[i] = reinterpret_cast<const float2*>(W1a)[i];
    for (int i = threadIdx.x; i < 64 * 32; i += blockDim.x)
        sWb[i] = reinterpret_cast<const float2*>(W1b)[i];
    if (threadIdx.x < 64) { sba[threadIdx.x] = b1a[threadIdx.x]; sbb[threadIdx.x] = b1b[threadIdx.x]; }
    __syncthreads();

    int warp = (blockIdx.x * blockDim.x + threadIdx.x) >> 5;
    int nw   = (gridDim.x * blockDim.x) >> 5;
    int lane = threadIdx.x & 31;
    int j    = lane * 2;

    for (int grp = warp; grp < N_GROUPS; grp += nw) {
        int n0 = grp * 8;
        float z[8][7];
#pragma unroll
        for (int m = 0; m < 8; m++) {
            uint4 ah = *reinterpret_cast<const uint4*>(g_aggr1h + (n0 + m) * 8);
            float2 a01 = __half22float2(*reinterpret_cast<__half2*>(&ah.x));
            float2 a23 = __half22float2(*reinterpret_cast<__half2*>(&ah.y));
            float2 a45 = __half22float2(*reinterpret_cast<__half2*>(&ah.z));
            float2 a67 = __half22float2(*reinterpret_cast<__half2*>(&ah.w));
            float as[7] = {a01.x, a01.y, a23.x, a23.y, a45.x, a45.y, a67.x};
#pragma unroll
            for (int k = 0; k < 7; k++)
                z[m][k] = g_x8[(n0 + m) * 8 + k] + as[k];
        }

        float t0[8], t1[8];
#pragma unroll
        for (int m = 0; m < 8; m++) { t0[m] = sba[j]; t1[m] = sba[j + 1]; }
#pragma unroll
        for (int k = 0; k < 7; k++) {
            float2 w = sWa[k * 32 + lane];
#pragma unroll
            for (int m = 0; m < 8; m++) {
                t0[m] += z[m][k] * w.x;
                t1[m] += z[m][k] * w.y;
            }
        }
#pragma unroll
        for (int m = 0; m < 8; m++) { t0[m] = fmaxf(t0[m], 0.f); t1[m] = fmaxf(t1[m], 0.f); }

        float a0[8], a1[8];
#pragma unroll
        for (int m = 0; m < 8; m++) { a0[m] = sbb[j]; a1[m] = sbb[j + 1]; }
#pragma unroll
        for (int k = 0; k < 64; k++) {
            float2 w = sWb[k * 32 + lane];
#pragma unroll
            for (int m = 0; m < 8; m++) {
                float tk = __shfl_sync(0xffffffffu, (k & 1) ? t1[m] : t0[m], k >> 1);
                a0[m] += tk * w.x;
                a1[m] += tk * w.y;
            }
        }
#pragma unroll
        for (int m = 0; m < 8; m++) {
            float v0 = fmaxf(a0[m], 0.f);   // outer relu from reference
            float v1 = fmaxf(a1[m], 0.f);
            *reinterpret_cast<float2*>(g_h1 + (n0 + m) * 64 + j) = make_float2(v0, v1);
            *reinterpret_cast<__half2*>(g_h1h + (n0 + m) * 64 + j) =
                __floats2half2_rn(v0, v1);
        }
    }
}

// ---------------- layer 2 edge pass (d = 64): 8 lanes per edge --------------
// EXACT R10 version (proven 56.7us): lane owns cols 8l..8l+7; weights in regs;
// pair-unrolled; ONE red.v4.f16x2 per lane per edge. No launch bounds.
#define E2_EPW 8
__global__ void edge2_kernel(const float* __restrict__ ea,
                             const int*   __restrict__ ei,
                             const float* __restrict__ We2,
                             const float* __restrict__ be2) {
    int l    = threadIdx.x & 7;                        // output slice 8l..8l+7
    int grp  = (blockIdx.x * blockDim.x + threadIdx.x) >> 3;
    int base = grp * E2_EPW;

    // per-lane weights: rows 0..3, cols 8l..8l+7 (two float4 per row) + bias
    float4 wa[4], wb[4];
#pragma unroll
    for (int r = 0; r < 4; r++) {
        wa[r] = __ldg(reinterpret_cast<const float4*>(We2 + r * 64) + 2 * l);
        wb[r] = __ldg(reinterpret_cast<const float4*>(We2 + r * 64) + 2 * l + 1);
    }
    float4 ba = __ldg(reinterpret_cast<const float4*>(be2) + 2 * l);
    float4 bc = __ldg(reinterpret_cast<const float4*>(be2) + 2 * l + 1);

#pragma unroll
    for (int i = 0; i < E2_EPW; i += 2) {
        int e0 = base + i;
        int2 s01 = __ldg(reinterpret_cast<const int2*>(ei + e0));
        int2 d01 = __ldg(reinterpret_cast<const int2*>(ei + N_EDGES + e0));
        float4 a0 = __ldg(reinterpret_cast<const float4*>(ea) + e0);
        float4 a1 = __ldg(reinterpret_cast<const float4*>(ea) + e0 + 1);
        uint4 hg0 = __ldg(reinterpret_cast<const uint4*>(g_h1h + s01.x * 64) + l);
        uint4 hg1 = __ldg(reinterpret_cast<const uint4*>(g_h1h + s01.y * 64) + l);

        // edge 0
        {
            float2 h0 = __half22float2(*reinterpret_cast<__half2*>(&hg0.x));
            float2 h1 = __half22float2(*reinterpret_cast<__half2*>(&hg0.y));
            float2 h2 = __half22float2(*reinterpret_cast<__half2*>(&hg0.z));
            float2 h3 = __half22float2(*reinterpret_cast<__half2*>(&hg0.w));
            float m0 = fmaxf(ba.x + a0.x*wa[0].x + a0.y*wa[1].x + a0.z*wa[2].x + a0.w*wa[3].x + h0.x, 0.f);
            float m1 = fmaxf(ba.y + a0.x*wa[0].y + a0.y*wa[1].y + a0.z*wa[2].y + a0.w*wa[3].y + h0.y, 0.f);
            float m2 = fmaxf(ba.z + a0.x*wa[0].z + a0.y*wa[1].z + a0.z*wa[2].z + a0.w*wa[3].z + h1.x, 0.f);
            float m3 = fmaxf(ba.w + a0.x*wa[0].w + a0.y*wa[1].w + a0.z*wa[2].w + a0.w*wa[3].w + h1.y, 0.f);
            float m4 = fmaxf(bc.x + a0.x*wb[0].x + a0.y*wb[1].x + a0.z*wb[2].x + a0.w*wb[3].x + h2.x, 0.f);
            float m5 = fmaxf(bc.y + a0.x*wb[0].y + a0.y*wb[1].y + a0.z*wb[2].y + a0.w*wb[3].y + h2.y, 0.f);
            float m6 = fmaxf(bc.z + a0.x*wb[0].z + a0.y*wb[1].z + a0.z*wb[2].z + a0.w*wb[3].z + h3.x, 0.f);
            float m7 = fmaxf(bc.w + a0.x*wb[0].w + a0.y*wb[1].w + a0.z*wb[2].w + a0.w*wb[3].w + h3.y, 0.f);
            __half2 p0 = __floats2half2_rn(m0, m1);
            __half2 p1 = __floats2half2_rn(m2, m3);
            __half2 p2 = __floats2half2_rn(m4, m5);
            __half2 p3 = __floats2half2_rn(m6, m7);
            __half* p = g_aggr2h + d01.x * 64 + l * 8;
            asm volatile("red.global.add.noftz.v4.f16x2 [%0], {%1, %2, %3, %4};"
                         :: "l"(p),
                            "r"(*reinterpret_cast<unsigned*>(&p0)),
                            "r"(*reinterpret_cast<unsigned*>(&p1)),
                            "r"(*reinterpret_cast<unsigned*>(&p2)),
                            "r"(*reinterpret_cast<unsigned*>(&p3)) : "memory");
        }
        // edge 1
        {
            float2 h0 = __half22float2(*reinterpret_cast<__half2*>(&hg1.x));
            float2 h1 = __half22float2(*reinterpret_cast<__half2*>(&hg1.y));
            float2 h2 = __half22float2(*reinterpret_cast<__half2*>(&hg1.z));
            float2 h3 = __half22float2(*reinterpret_cast<__half2*>(&hg1.w));
            float m0 = fmaxf(ba.x + a1.x*wa[0].x + a1.y*wa[1].x + a1.z*wa[2].x + a1.w*wa[3].x + h0.x, 0.f);
            float m1 = fmaxf(ba.y + a1.x*wa[0].y + a1.y*wa[1].y + a1.z*wa[2].y + a1.w*wa[3].y + h0.y, 0.f);
            float m2 = fmaxf(ba.z + a1.x*wa[0].z + a1.y*wa[1].z + a1.z*wa[2].z + a1.w*wa[3].z + h1.x, 0.f);
            float m3 = fmaxf(ba.w + a1.x*wa[0].w + a1.y*wa[1].w + a1.z*wa[2].w + a1.w*wa[3].w + h1.y, 0.f);
            float m4 = fmaxf(bc.x + a1.x*wb[0].x + a1.y*wb[1].x + a1.z*wb[2].x + a1.w*wb[3].x + h2.x, 0.f);
            float m5 = fmaxf(bc.y + a1.x*wb[0].y + a1.y*wb[1].y + a1.z*wb[2].y + a1.w*wb[3].y + h2.y, 0.f);
            float m6 = fmaxf(bc.z + a1.x*wb[0].z + a1.y*wb[1].z + a1.z*wb[2].z + a1.w*wb[3].z + h3.x, 0.f);
            float m7 = fmaxf(bc.w + a1.x*wb[0].w + a1.y*wb[1].w + a1.z*wb[2].w + a1.w*wb[3].w + h3.y, 0.f);
            __half2 p0 = __floats2half2_rn(m0, m1);
            __half2 p1 = __floats2half2_rn(m2, m3);
            __half2 p2 = __floats2half2_rn(m4, m5);
            __half2 p3 = __floats2half2_rn(m6, m7);
            __half* p = g_aggr2h + d01.y * 64 + l * 8;
            asm volatile("red.global.add.noftz.v4.f16x2 [%0], {%1, %2, %3, %4};"
                         :: "l"(p),
                            "r"(*reinterpret_cast<unsigned*>(&p0)),
                            "r"(*reinterpret_cast<unsigned*>(&p1)),
                            "r"(*reinterpret_cast<unsigned*>(&p2)),
                            "r"(*reinterpret_cast<unsigned*>(&p3)) : "memory");
        }
    }
}

// ---------------- layer 2 node MLP (64->64->64) + pool, 8-node blocked -----
__global__ void node2pool_kernel(const int*   __restrict__ batch,
                                 const float* __restrict__ W2a,
                                 const float* __restrict__ b2a,
                                 const float* __restrict__ W2b,
                                 const float* __restrict__ b2b) {
    __shared__ float2 sWa[64 * 32];
    __shared__ float2 sWb[64 * 32];
    __shared__ float  sba[64];
    __shared__ float  sbb[64];
    for (int i = threadIdx.x; i < 64 * 32; i += blockDim.x) {
        sWa[i] = reinterpret_cast<const float2*>(W2a)[i];
        sWb[i] = reinterpret_cast<const float2*>(W2b)[i];
    }
    if (threadIdx.x < 64) { sba[threadIdx.x] = b2a[threadIdx.x]; sbb[threadIdx.x] = b2b[threadIdx.x]; }
    __syncthreads();

    int warp = (blockIdx.x * blockDim.x + threadIdx.x) >> 5;
    int nw   = (gridDim.x * blockDim.x) >> 5;
    int lane = threadIdx.x & 31;
    int j    = lane * 2;

    for (int grp = warp; grp < N_GROUPS; grp += nw) {
        int n0 = grp * 8;
        float z0[8], z1[8];
#pragma unroll
        for (int m = 0; m < 8; m++) {
            float2 hv = *reinterpret_cast<const float2*>(g_h1 + (n0 + m) * 64 + j);
            float2 av = __half22float2(
                *reinterpret_cast<const __half2*>(g_aggr2h + (n0 + m) * 64 + j));
            z0[m] = hv.x + av.x;
            z1[m] = hv.y + av.y;
        }

        float t0[8], t1[8];
#pragma unroll
        for (int m = 0; m < 8; m++) { t0[m] = sba[j]; t1[m] = sba[j + 1]; }
#pragma unroll
        for (int k = 0; k < 64; k++) {
            float2 w = sWa[k * 32 + lane];
#pragma unroll
            for (int m = 0; m < 8; m++) {
                float zk = __shfl_sync(0xffffffffu, (k & 1) ? z1[m] : z0[m], k >> 1);
                t0[m] += zk * w.x;
                t1[m] += zk * w.y;
            }
        }
#pragma unroll
        for (int m = 0; m < 8; m++) { t0[m] = fmaxf(t0[m], 0.f); t1[m] = fmaxf(t1[m], 0.f); }

        float a0[8], a1[8];
#pragma unroll
        for (int m = 0; m < 8; m++) { a0[m] = sbb[j]; a1[m] = sbb[j + 1]; }
#pragma unroll
        for (int k = 0; k < 64; k++) {
            float2 w = sWb[k * 32 + lane];
#pragma unroll
            for (int m = 0; m < 8; m++) {
                float tk = __shfl_sync(0xffffffffu, (k & 1) ? t1[m] : t0[m], k >> 1);
                a0[m] += tk * w.x;
                a1[m] += tk * w.y;
            }
        }
#pragma unroll
        for (int m = 0; m < 8; m++) {
            float v0 = fmaxf(a0[m], 0.f);   // outer relu from reference
            float v1 = fmaxf(a1[m], 0.f);
            int g = batch[n0 + m];
            float* p = g_sums + g * 64 + j;
            asm volatile("red.global.add.v2.f32 [%0], {%1, %2};"
                         :: "l"(p), "f"(v0), "f"(v1) : "memory");
            if (lane == 0) atomicAdd(&g_cnt[g], 1.0f);
        }
    }
}

// ---------------- final FC: pooled[G,64] @ Wfc[64,12] + bfc -----------------
__global__ void fc_kernel(const float* __restrict__ Wfc,
                          const float* __restrict__ bfc,
                          float* __restrict__ out) {
    int i = blockIdx.x * blockDim.x + threadIdx.x;
    if (i >= N_GRAPHS * 12) return;
    int g = i / 12;
    int c = i % 12;
    float inv = 1.0f / fmaxf(g_cnt[g], 1.0f);
    float acc = 0.f;
#pragma unroll
    for (int k = 0; k < 64; k++)
        acc += g_sums[g * 64 + k] * Wfc[k * 12 + c];
    out[i] = bfc[c] + inv * acc;
}

// ---------------- launch ----------------------------------------------------
extern "C" void kernel_launch(void* const* d_in, const int* in_sizes, int n_in,
                              void* d_out, int out_size) {
    const float* x    = (const float*)d_in[0];
    const float* ea   = (const float*)d_in[1];
    const int*   ei   = (const int*)  d_in[2];
    const int*   batch= (const int*)  d_in[3];
    const float* We1  = (const float*)d_in[4];
    const float* be1  = (const float*)d_in[5];
    const float* W1a  = (const float*)d_in[6];
    const float* b1a  = (const float*)d_in[7];
    const float* W1b  = (const float*)d_in[8];
    const float* b1b  = (const float*)d_in[9];
    const float* We2  = (const float*)d_in[10];
    const float* be2  = (const float*)d_in[11];
    const float* W2a  = (const float*)d_in[12];
    const float* b2a  = (const float*)d_in[13];
    const float* W2b  = (const float*)d_in[14];
    const float* b2b  = (const float*)d_in[15];
    const float* Wfc  = (const float*)d_in[16];
    const float* bfc  = (const float*)d_in[17];
    float* out = (float*)d_out;

    zero_kernel<<<(ZSM + 255) / 256, 256>>>(x);
    edge1_kernel<<<1184, 256>>>(ea, ei, We1, be1);
    node1_kernel<<<592, 256>>>(W1a, b1a, W1b, b1b);
    edge2_kernel<<<(N_EDGES / E2_EPW) * 8 / 256, 256>>>(ea, ei, We2, be2);
    node2pool_kernel<<<592, 256>>>(batch, W2a, b2a, W2b, b2b);
    fc_kernel<<<(N_GRAPHS * 12 + 255) / 256, 256>>>(Wfc, bfc, out);
}

// round 13
// speedup vs baseline: 1.1368x; 1.0175x over previous
#include <cuda_runtime.h>
#include <cuda_fp16.h>

#define N_NODES  50000
#define N_EDGES  1600000
#define N_GRAPHS 1000

// ---------------- scratch (device globals; no allocation allowed) ----------
__device__ __align__(16) float  g_x8[N_NODES * 8];      // padded node features (fp32)
__device__ __align__(16) __half g_x8h[N_NODES * 8];     // padded node features (fp16)
__device__ __align__(16) __half g_aggr1h[N_NODES * 8];  // layer1 aggregation (fp16 atomics)
__device__ __align__(16) __half g_h1h[N_NODES * 64];    // layer1 output (fp16 only)
__device__ __align__(16) __half g_aggr2h[N_NODES * 64]; // layer2 aggregation (fp16 atomics)
__device__ __align__(16) float  g_sums[N_GRAPHS * 64];  // pooled sums
__device__ __align__(16) float  g_cnt[N_GRAPHS];        // per-graph node counts

// ---------------- zero scratch + pad x ---------------------------------------
#define ZX  (N_NODES * 2)
#define ZA2 (ZX + N_NODES * 8)
#define ZSM (ZA2 + N_GRAPHS * 16)
__global__ void zero_kernel(const float* __restrict__ x) {
    int i = blockIdx.x * blockDim.x + threadIdx.x;
    if (i < ZX) {
        int node = i >> 1, h = i & 1;
        int base = node * 7 + h * 4;
        float4 v;
        v.x = __ldg(&x[base + 0]);
        v.y = __ldg(&x[base + 1]);
        v.z = __ldg(&x[base + 2]);
        v.w = (h == 0) ? __ldg(&x[base + 3]) : 0.f;   // j=7 pad
        reinterpret_cast<float4*>(g_x8)[i] = v;
        __half2 p0 = __floats2half2_rn(v.x, v.y);
        __half2 p1 = __floats2half2_rn(v.z, v.w);
        uint2 u;
        u.x = *reinterpret_cast<unsigned*>(&p0);
        u.y = *reinterpret_cast<unsigned*>(&p1);
        *reinterpret_cast<uint2*>(reinterpret_cast<char*>(g_x8h) + node * 16 + h * 8) = u;
        if (i < N_NODES)
            reinterpret_cast<uint4*>(g_aggr1h)[i] = make_uint4(0, 0, 0, 0);
    } else if (i < ZA2) {
        reinterpret_cast<uint4*>(g_aggr2h)[i - ZX] = make_uint4(0, 0, 0, 0);
    } else if (i < ZSM) {
        reinterpret_cast<float4*>(g_sums)[i - ZA2] = make_float4(0.f, 0.f, 0.f, 0.f);
    }
    if (i < N_GRAPHS) g_cnt[i] = 0.f;
}

// ---------------- layer 1 edge pass (d = 7): ONE v4.f16x2 red per edge ------
__global__ void edge1_kernel(const float* __restrict__ ea,
                             const int*   __restrict__ ei,
                             const float* __restrict__ We1,
                             const float* __restrict__ be1) {
    float w[4][7], b[7];
#pragma unroll
    for (int i = 0; i < 4; i++)
#pragma unroll
        for (int j = 0; j < 7; j++)
            w[i][j] = __ldg(&We1[i * 7 + j]);
#pragma unroll
    for (int j = 0; j < 7; j++) b[j] = __ldg(&be1[j]);

    int t  = blockIdx.x * blockDim.x + threadIdx.x;
    int nt = gridDim.x * blockDim.x;
    for (int e = t; e < N_EDGES; e += nt) {
        int src = __ldg(&ei[e]);
        int dst = __ldg(&ei[N_EDGES + e]);
        float4 a = __ldg(reinterpret_cast<const float4*>(ea) + e);
        uint4 xh = __ldg(reinterpret_cast<const uint4*>(g_x8h) + src);
        float2 x01 = __half22float2(*reinterpret_cast<__half2*>(&xh.x));
        float2 x23 = __half22float2(*reinterpret_cast<__half2*>(&xh.y));
        float2 x45 = __half22float2(*reinterpret_cast<__half2*>(&xh.z));
        float2 x67 = __half22float2(*reinterpret_cast<__half2*>(&xh.w));
        float xs[8] = {x01.x, x01.y, x23.x, x23.y, x45.x, x45.y, x67.x, 0.f};
        float v[8];
#pragma unroll
        for (int j = 0; j < 7; j++) {
            float m = b[j] + a.x * w[0][j] + a.y * w[1][j]
                            + a.z * w[2][j] + a.w * w[3][j];
            v[j] = fmaxf(m + xs[j], 0.f);
        }
        v[7] = 0.f;
        __half2 p0 = __floats2half2_rn(v[0], v[1]);
        __half2 p1 = __floats2half2_rn(v[2], v[3]);
        __half2 p2 = __floats2half2_rn(v[4], v[5]);
        __half2 p3 = __floats2half2_rn(v[6], v[7]);
        __half* p = g_aggr1h + dst * 8;
        asm volatile("red.global.add.noftz.v4.f16x2 [%0], {%1, %2, %3, %4};"
                     :: "l"(p),
                        "r"(*reinterpret_cast<unsigned*>(&p0)),
                        "r"(*reinterpret_cast<unsigned*>(&p1)),
                        "r"(*reinterpret_cast<unsigned*>(&p2)),
                        "r"(*reinterpret_cast<unsigned*>(&p3)) : "memory");
    }
}

// ---------------- layer 1 node MLP: 7 -> 64 -> 64, 4-node blocked ----------
#define N_GROUPS (N_NODES / 4)
__global__ void node1_kernel(const float* __restrict__ W1a,
                             const float* __restrict__ b1a,
                             const float* __restrict__ W1b,
                             const float* __restrict__ b1b) {
    __shared__ float2 sWa[7 * 32];
    __shared__ float2 sWb[64 * 32];
    __shared__ float  sba[64];
    __shared__ float  sbb[64];
    for (int i = threadIdx.x; i < 7 * 32; i += blockDim.x)
        sWa[i] = reinterpret_cast<const float2*>(W1a)[i];
    for (int i = threadIdx.x; i < 64 * 32; i += blockDim.x)
        sWb[i] = reinterpret_cast<const float2*>(W1b)[i];
    if (threadIdx.x < 64) { sba[threadIdx.x] = b1a[threadIdx.x]; sbb[threadIdx.x] = b1b[threadIdx.x]; }
    __syncthreads();

    int warp = (blockIdx.x * blockDim.x + threadIdx.x) >> 5;
    int nw   = (gridDim.x * blockDim.x) >> 5;
    int lane = threadIdx.x & 31;
    int j    = lane * 2;

    for (int grp = warp; grp < N_GROUPS; grp += nw) {
        int n0 = grp * 4;
        float z[4][7];
#pragma unroll
        for (int m = 0; m < 4; m++) {
            uint4 ah = *reinterpret_cast<const uint4*>(g_aggr1h + (n0 + m) * 8);
            float2 a01 = __half22float2(*reinterpret_cast<__half2*>(&ah.x));
            float2 a23 = __half22float2(*reinterpret_cast<__half2*>(&ah.y));
            float2 a45 = __half22float2(*reinterpret_cast<__half2*>(&ah.z));
            float2 a67 = __half22float2(*reinterpret_cast<__half2*>(&ah.w));
            float as[7] = {a01.x, a01.y, a23.x, a23.y, a45.x, a45.y, a67.x};
#pragma unroll
            for (int k = 0; k < 7; k++)
                z[m][k] = g_x8[(n0 + m) * 8 + k] + as[k];
        }

        float t0[4], t1[4];
#pragma unroll
        for (int m = 0; m < 4; m++) { t0[m] = sba[j]; t1[m] = sba[j + 1]; }
#pragma unroll
        for (int k = 0; k < 7; k++) {
            float2 w = sWa[k * 32 + lane];
#pragma unroll
            for (int m = 0; m < 4; m++) {
                t0[m] += z[m][k] * w.x;
                t1[m] += z[m][k] * w.y;
            }
        }
#pragma unroll
        for (int m = 0; m < 4; m++) { t0[m] = fmaxf(t0[m], 0.f); t1[m] = fmaxf(t1[m], 0.f); }

        float a0[4], a1[4];
#pragma unroll
        for (int m = 0; m < 4; m++) { a0[m] = sbb[j]; a1[m] = sbb[j + 1]; }
#pragma unroll
        for (int k = 0; k < 64; k++) {
            float2 w = sWb[k * 32 + lane];
#pragma unroll
            for (int m = 0; m < 4; m++) {
                float tk = __shfl_sync(0xffffffffu, (k & 1) ? t1[m] : t0[m], k >> 1);
                a0[m] += tk * w.x;
                a1[m] += tk * w.y;
            }
        }
#pragma unroll
        for (int m = 0; m < 4; m++) {
            float v0 = fmaxf(a0[m], 0.f);   // outer relu from reference
            float v1 = fmaxf(a1[m], 0.f);
            // fp16-only h1 (consumed at fp16 by edge2 AND node2pool)
            *reinterpret_cast<__half2*>(g_h1h + (n0 + m) * 64 + j) =
                __floats2half2_rn(v0, v1);
        }
    }
}

// ---------------- layer 2 edge pass (d = 64): 8 lanes per edge --------------
// EXACT R10 version (proven 56.5us): lane owns cols 8l..8l+7; weights in regs;
// pair-unrolled; ONE red.v4.f16x2 per lane per edge. No launch bounds.
#define E2_EPW 8
__global__ void edge2_kernel(const float* __restrict__ ea,
                             const int*   __restrict__ ei,
                             const float* __restrict__ We2,
                             const float* __restrict__ be2) {
    int l    = threadIdx.x & 7;                        // output slice 8l..8l+7
    int grp  = (blockIdx.x * blockDim.x + threadIdx.x) >> 3;
    int base = grp * E2_EPW;

    // per-lane weights: rows 0..3, cols 8l..8l+7 (two float4 per row) + bias
    float4 wa[4], wb[4];
#pragma unroll
    for (int r = 0; r < 4; r++) {
        wa[r] = __ldg(reinterpret_cast<const float4*>(We2 + r * 64) + 2 * l);
        wb[r] = __ldg(reinterpret_cast<const float4*>(We2 + r * 64) + 2 * l + 1);
    }
    float4 ba = __ldg(reinterpret_cast<const float4*>(be2) + 2 * l);
    float4 bc = __ldg(reinterpret_cast<const float4*>(be2) + 2 * l + 1);

#pragma unroll
    for (int i = 0; i < E2_EPW; i += 2) {
        int e0 = base + i;
        int2 s01 = __ldg(reinterpret_cast<const int2*>(ei + e0));
        int2 d01 = __ldg(reinterpret_cast<const int2*>(ei + N_EDGES + e0));
        float4 a0 = __ldg(reinterpret_cast<const float4*>(ea) + e0);
        float4 a1 = __ldg(reinterpret_cast<const float4*>(ea) + e0 + 1);
        uint4 hg0 = __ldg(reinterpret_cast<const uint4*>(g_h1h + s01.x * 64) + l);
        uint4 hg1 = __ldg(reinterpret_cast<const uint4*>(g_h1h + s01.y * 64) + l);

        // edge 0
        {
            float2 h0 = __half22float2(*reinterpret_cast<__half2*>(&hg0.x));
            float2 h1 = __half22float2(*reinterpret_cast<__half2*>(&hg0.y));
            float2 h2 = __half22float2(*reinterpret_cast<__half2*>(&hg0.z));
            float2 h3 = __half22float2(*reinterpret_cast<__half2*>(&hg0.w));
            float m0 = fmaxf(ba.x + a0.x*wa[0].x + a0.y*wa[1].x + a0.z*wa[2].x + a0.w*wa[3].x + h0.x, 0.f);
            float m1 = fmaxf(ba.y + a0.x*wa[0].y + a0.y*wa[1].y + a0.z*wa[2].y + a0.w*wa[3].y + h0.y, 0.f);
            float m2 = fmaxf(ba.z + a0.x*wa[0].z + a0.y*wa[1].z + a0.z*wa[2].z + a0.w*wa[3].z + h1.x, 0.f);
            float m3 = fmaxf(ba.w + a0.x*wa[0].w + a0.y*wa[1].w + a0.z*wa[2].w + a0.w*wa[3].w + h1.y, 0.f);
            float m4 = fmaxf(bc.x + a0.x*wb[0].x + a0.y*wb[1].x + a0.z*wb[2].x + a0.w*wb[3].x + h2.x, 0.f);
            float m5 = fmaxf(bc.y + a0.x*wb[0].y + a0.y*wb[1].y + a0.z*wb[2].y + a0.w*wb[3].y + h2.y, 0.f);
            float m6 = fmaxf(bc.z + a0.x*wb[0].z + a0.y*wb[1].z + a0.z*wb[2].z + a0.w*wb[3].z + h3.x, 0.f);
            float m7 = fmaxf(bc.w + a0.x*wb[0].w + a0.y*wb[1].w + a0.z*wb[2].w + a0.w*wb[3].w + h3.y, 0.f);
            __half2 p0 = __floats2half2_rn(m0, m1);
            __half2 p1 = __floats2half2_rn(m2, m3);
            __half2 p2 = __floats2half2_rn(m4, m5);
            __half2 p3 = __floats2half2_rn(m6, m7);
            __half* p = g_aggr2h + d01.x * 64 + l * 8;
            asm volatile("red.global.add.noftz.v4.f16x2 [%0], {%1, %2, %3, %4};"
                         :: "l"(p),
                            "r"(*reinterpret_cast<unsigned*>(&p0)),
                            "r"(*reinterpret_cast<unsigned*>(&p1)),
                            "r"(*reinterpret_cast<unsigned*>(&p2)),
                            "r"(*reinterpret_cast<unsigned*>(&p3)) : "memory");
        }
        // edge 1
        {
            float2 h0 = __half22float2(*reinterpret_cast<__half2*>(&hg1.x));
            float2 h1 = __half22float2(*reinterpret_cast<__half2*>(&hg1.y));
            float2 h2 = __half22float2(*reinterpret_cast<__half2*>(&hg1.z));
            float2 h3 = __half22float2(*reinterpret_cast<__half2*>(&hg1.w));
            float m0 = fmaxf(ba.x + a1.x*wa[0].x + a1.y*wa[1].x + a1.z*wa[2].x + a1.w*wa[3].x + h0.x, 0.f);
            float m1 = fmaxf(ba.y + a1.x*wa[0].y + a1.y*wa[1].y + a1.z*wa[2].y + a1.w*wa[3].y + h0.y, 0.f);
            float m2 = fmaxf(ba.z + a1.x*wa[0].z + a1.y*wa[1].z + a1.z*wa[2].z + a1.w*wa[3].z + h1.x, 0.f);
            float m3 = fmaxf(ba.w + a1.x*wa[0].w + a1.y*wa[1].w + a1.z*wa[2].w + a1.w*wa[3].w + h1.y, 0.f);
            float m4 = fmaxf(bc.x + a1.x*wb[0].x + a1.y*wb[1].x + a1.z*wb[2].x + a1.w*wb[3].x + h2.x, 0.f);
            float m5 = fmaxf(bc.y + a1.x*wb[0].y + a1.y*wb[1].y + a1.z*wb[2].y + a1.w*wb[3].y + h2.y, 0.f);
            float m6 = fmaxf(bc.z + a1.x*wb[0].z + a1.y*wb[1].z + a1.z*wb[2].z + a1.w*wb[3].z + h3.x, 0.f);
            float m7 = fmaxf(bc.w + a1.x*wb[0].w + a1.y*wb[1].w + a1.z*wb[2].w + a1.w*wb[3].w + h3.y, 0.f);
            __half2 p0 = __floats2half2_rn(m0, m1);
            __half2 p1 = __floats2half2_rn(m2, m3);
            __half2 p2 = __floats2half2_rn(m4, m5);
            __half2 p3 = __floats2half2_rn(m6, m7);
            __half* p = g_aggr2h + d01.y * 64 + l * 8;
            asm volatile("red.global.add.noftz.v4.f16x2 [%0], {%1, %2, %3, %4};"
                         :: "l"(p),
                            "r"(*reinterpret_cast<unsigned*>(&p0)),
                            "r"(*reinterpret_cast<unsigned*>(&p1)),
                            "r"(*reinterpret_cast<unsigned*>(&p2)),
                            "r"(*reinterpret_cast<unsigned*>(&p3)) : "memory");
        }
    }
}

// ---------------- layer 2 node MLP (64->64->64) + pool, 4-node blocked -----
__global__ void node2pool_kernel(const int*   __restrict__ batch,
                                 const float* __restrict__ W2a,
                                 const float* __restrict__ b2a,
                                 const float* __restrict__ W2b,
                                 const float* __restrict__ b2b) {
    __shared__ float2 sWa[64 * 32];
    __shared__ float2 sWb[64 * 32];
    __shared__ float  sba[64];
    __shared__ float  sbb[64];
    for (int i = threadIdx.x; i < 64 * 32; i += blockDim.x) {
        sWa[i] = reinterpret_cast<const float2*>(W2a)[i];
        sWb[i] = reinterpret_cast<const float2*>(W2b)[i];
    }
    if (threadIdx.x < 64) { sba[threadIdx.x] = b2a[threadIdx.x]; sbb[threadIdx.x] = b2b[threadIdx.x]; }
    __syncthreads();

    int warp = (blockIdx.x * blockDim.x + threadIdx.x) >> 5;
    int nw   = (gridDim.x * blockDim.x) >> 5;
    int lane = threadIdx.x & 31;
    int j    = lane * 2;

    for (int grp = warp; grp < N_GROUPS; grp += nw) {
        int n0 = grp * 4;
        float z0[4], z1[4];
#pragma unroll
        for (int m = 0; m < 4; m++) {
            float2 hv = __half22float2(
                *reinterpret_cast<const __half2*>(g_h1h + (n0 + m) * 64 + j));
            float2 av = __half22float2(
                *reinterpret_cast<const __half2*>(g_aggr2h + (n0 + m) * 64 + j));
            z0[m] = hv.x + av.x;
            z1[m] = hv.y + av.y;
        }

        float t0[4], t1[4];
#pragma unroll
        for (int m = 0; m < 4; m++) { t0[m] = sba[j]; t1[m] = sba[j + 1]; }
#pragma unroll
        for (int k = 0; k < 64; k++) {
            float2 w = sWa[k * 32 + lane];
#pragma unroll
            for (int m = 0; m < 4; m++) {
                float zk = __shfl_sync(0xffffffffu, (k & 1) ? z1[m] : z0[m], k >> 1);
                t0[m] += zk * w.x;
                t1[m] += zk * w.y;
            }
        }
#pragma unroll
        for (int m = 0; m < 4; m++) { t0[m] = fmaxf(t0[m], 0.f); t1[m] = fmaxf(t1[m], 0.f); }

        float a0[4], a1[4];
#pragma unroll
        for (int m = 0; m < 4; m++) { a0[m] = sbb[j]; a1[m] = sbb[j + 1]; }
#pragma unroll
        for (int k = 0; k < 64; k++) {
            float2 w = sWb[k * 32 + lane];
#pragma unroll
            for (int m = 0; m < 4; m++) {
                float tk = __shfl_sync(0xffffffffu, (k & 1) ? t1[m] : t0[m], k >> 1);
                a0[m] += tk * w.x;
                a1[m] += tk * w.y;
            }
        }
#pragma unroll
        for (int m = 0; m < 4; m++) {
            float v0 = fmaxf(a0[m], 0.f);   // outer relu from reference
            float v1 = fmaxf(a1[m], 0.f);
            int g = batch[n0 + m];
            float* p = g_sums + g * 64 + j;
            asm volatile("red.global.add.v2.f32 [%0], {%1, %2};"
                         :: "l"(p), "f"(v0), "f"(v1) : "memory");
            if (lane == 0) atomicAdd(&g_cnt[g], 1.0f);
        }
    }
}

// ---------------- final FC: pooled[G,64] @ Wfc[64,12] + bfc -----------------
__global__ void fc_kernel(const float* __restrict__ Wfc,
                          const float* __restrict__ bfc,
                          float* __restrict__ out) {
    int i = blockIdx.x * blockDim.x + threadIdx.x;
    if (i >= N_GRAPHS * 12) return;
    int g = i / 12;
    int c = i % 12;
    float inv = 1.0f / fmaxf(g_cnt[g], 1.0f);
    float acc = 0.f;
#pragma unroll
    for (int k = 0; k < 64; k++)
        acc += g_sums[g * 64 + k] * Wfc[k * 12 + c];
    out[i] = bfc[c] + inv * acc;
}

// ---------------- launch ----------------------------------------------------
extern "C" void kernel_launch(void* const* d_in, const int* in_sizes, int n_in,
                              void* d_out, int out_size) {
    const float* x    = (const float*)d_in[0];
    const float* ea   = (const float*)d_in[1];
    const int*   ei   = (const int*)  d_in[2];
    const int*   batch= (const int*)  d_in[3];
    const float* We1  = (const float*)d_in[4];
    const float* be1  = (const float*)d_in[5];
    const float* W1a  = (const float*)d_in[6];
    const float* b1a  = (const float*)d_in[7];
    const float* W1b  = (const float*)d_in[8];
    const float* b1b  = (const float*)d_in[9];
    const float* We2  = (const float*)d_in[10];
    const float* be2  = (const float*)d_in[11];
    const float* W2a  = (const float*)d_in[12];
    const float* b2a  = (const float*)d_in[13];
    const float* W2b  = (const float*)d_in[14];
    const float* b2b  = (const float*)d_in[15];
    const float* Wfc  = (const float*)d_in[16];
    const float* bfc  = (const float*)d_in[17];
    float* out = (float*)d_out;

    zero_kernel<<<(ZSM + 255) / 256, 256>>>(x);
    edge1_kernel<<<1184, 256>>>(ea, ei, We1, be1);
    node1_kernel<<<592, 256>>>(W1a, b1a, W1b, b1b);
    edge2_kernel<<<(N_EDGES / E2_EPW) * 8 / 256, 256>>>(ea, ei, We2, be2);
    node2pool_kernel<<<592, 256>>>(batch, W2a, b2a, W2b, b2b);
    fc_kernel<<<(N_GRAPHS * 12 + 255) / 256, 256>>>(Wfc, bfc, out);
}

// round 14
// speedup vs baseline: 1.2494x; 1.0991x over previous
#include <cuda_runtime.h>
#include <cuda_fp16.h>

#define N_NODES  50000
#define N_EDGES  1600000
#define N_GRAPHS 1000

// ---------------- scratch (device globals; no allocation allowed) ----------
__device__ __align__(16) float  g_x8[N_NODES * 8];      // padded node features (fp32)
__device__ __align__(16) __half g_x8h[N_NODES * 8];     // padded node features (fp16)
__device__ __align__(16) __half g_aggr1h[N_NODES * 8];  // layer1 aggregation (fp16 atomics)
__device__ __align__(16) __half g_h1h[N_NODES * 64];    // layer1 output (fp16 only)
__device__ __align__(16) __half g_aggr2h[N_NODES * 64]; // layer2 aggregation (fp16 atomics)
__device__ __align__(16) float  g_sums[N_GRAPHS * 64];  // pooled sums
__device__ __align__(16) float  g_cnt[N_GRAPHS];        // per-graph node counts

// ---------------- zero scratch + pad x ---------------------------------------
#define ZX  (N_NODES * 2)
#define ZA2 (ZX + N_NODES * 8)
#define ZSM (ZA2 + N_GRAPHS * 16)
__global__ void zero_kernel(const float* __restrict__ x) {
    int i = blockIdx.x * blockDim.x + threadIdx.x;
    if (i < ZX) {
        int node = i >> 1, h = i & 1;
        int base = node * 7 + h * 4;
        float4 v;
        v.x = __ldg(&x[base + 0]);
        v.y = __ldg(&x[base + 1]);
        v.z = __ldg(&x[base + 2]);
        v.w = (h == 0) ? __ldg(&x[base + 3]) : 0.f;   // j=7 pad
        reinterpret_cast<float4*>(g_x8)[i] = v;
        __half2 p0 = __floats2half2_rn(v.x, v.y);
        __half2 p1 = __floats2half2_rn(v.z, v.w);
        uint2 u;
        u.x = *reinterpret_cast<unsigned*>(&p0);
        u.y = *reinterpret_cast<unsigned*>(&p1);
        *reinterpret_cast<uint2*>(reinterpret_cast<char*>(g_x8h) + node * 16 + h * 8) = u;
        if (i < N_NODES)
            reinterpret_cast<uint4*>(g_aggr1h)[i] = make_uint4(0, 0, 0, 0);
    } else if (i < ZA2) {
        reinterpret_cast<uint4*>(g_aggr2h)[i - ZX] = make_uint4(0, 0, 0, 0);
    } else if (i < ZSM) {
        reinterpret_cast<float4*>(g_sums)[i - ZA2] = make_float4(0.f, 0.f, 0.f, 0.f);
    }
    if (i < N_GRAPHS) g_cnt[i] = 0.f;
}

// ---------------- layer 1 edge pass (d = 7): ONE v4.f16x2 red per edge ------
__global__ void edge1_kernel(const float* __restrict__ ea,
                             const int*   __restrict__ ei,
                             const float* __restrict__ We1,
                             const float* __restrict__ be1) {
    float w[4][7], b[7];
#pragma unroll
    for (int i = 0; i < 4; i++)
#pragma unroll
        for (int j = 0; j < 7; j++)
            w[i][j] = __ldg(&We1[i * 7 + j]);
#pragma unroll
    for (int j = 0; j < 7; j++) b[j] = __ldg(&be1[j]);

    int t  = blockIdx.x * blockDim.x + threadIdx.x;
    int nt = gridDim.x * blockDim.x;
    for (int e = t; e < N_EDGES; e += nt) {
        int src = __ldg(&ei[e]);
        int dst = __ldg(&ei[N_EDGES + e]);
        float4 a = __ldg(reinterpret_cast<const float4*>(ea) + e);
        uint4 xh = __ldg(reinterpret_cast<const uint4*>(g_x8h) + src);
        float2 x01 = __half22float2(*reinterpret_cast<__half2*>(&xh.x));
        float2 x23 = __half22float2(*reinterpret_cast<__half2*>(&xh.y));
        float2 x45 = __half22float2(*reinterpret_cast<__half2*>(&xh.z));
        float2 x67 = __half22float2(*reinterpret_cast<__half2*>(&xh.w));
        float xs[8] = {x01.x, x01.y, x23.x, x23.y, x45.x, x45.y, x67.x, 0.f};
        float v[8];
#pragma unroll
        for (int j = 0; j < 7; j++) {
            float m = b[j] + a.x * w[0][j] + a.y * w[1][j]
                            + a.z * w[2][j] + a.w * w[3][j];
            v[j] = fmaxf(m + xs[j], 0.f);
        }
        v[7] = 0.f;
        __half2 p0 = __floats2half2_rn(v[0], v[1]);
        __half2 p1 = __floats2half2_rn(v[2], v[3]);
        __half2 p2 = __floats2half2_rn(v[4], v[5]);
        __half2 p3 = __floats2half2_rn(v[6], v[7]);
        __half* p = g_aggr1h + dst * 8;
        asm volatile("red.global.add.noftz.v4.f16x2 [%0], {%1, %2, %3, %4};"
                     :: "l"(p),
                        "r"(*reinterpret_cast<unsigned*>(&p0)),
                        "r"(*reinterpret_cast<unsigned*>(&p1)),
                        "r"(*reinterpret_cast<unsigned*>(&p2)),
                        "r"(*reinterpret_cast<unsigned*>(&p3)) : "memory");
    }
}

// ---------------- layer 1 node MLP: 7 -> 64 -> 64, 4-node blocked ----------
// layer-2 broadcast via warp-private transposed smem tile (LDS.128, no SHFL)
#define N_GROUPS (N_NODES / 4)
__global__ void node1_kernel(const float* __restrict__ W1a,
                             const float* __restrict__ b1a,
                             const float* __restrict__ W1b,
                             const float* __restrict__ b1b) {
    __shared__ float2 sWa[7 * 32];
    __shared__ float2 sWb[64 * 32];
    __shared__ float  sba[64];
    __shared__ float  sbb[64];
    __shared__ float4 sT[8 * 64];     // per-warp 64x4 transposed activations
    for (int i = threadIdx.x; i < 7 * 32; i += blockDim.x)
        sWa[i] = reinterpret_cast<const float2*>(W1a)[i];
    for (int i = threadIdx.x; i < 64 * 32; i += blockDim.x)
        sWb[i] = reinterpret_cast<const float2*>(W1b)[i];
    if (threadIdx.x < 64) { sba[threadIdx.x] = b1a[threadIdx.x]; sbb[threadIdx.x] = b1b[threadIdx.x]; }
    __syncthreads();

    int warp = (blockIdx.x * blockDim.x + threadIdx.x) >> 5;
    int nw   = (gridDim.x * blockDim.x) >> 5;
    int lane = threadIdx.x & 31;
    int j    = lane * 2;
    int wb   = (threadIdx.x >> 5) * 64;   // warp's smem tile base

    for (int grp = warp; grp < N_GROUPS; grp += nw) {
        int n0 = grp * 4;
        float z[4][7];
#pragma unroll
        for (int m = 0; m < 4; m++) {
            uint4 ah = *reinterpret_cast<const uint4*>(g_aggr1h + (n0 + m) * 8);
            float2 a01 = __half22float2(*reinterpret_cast<__half2*>(&ah.x));
            float2 a23 = __half22float2(*reinterpret_cast<__half2*>(&ah.y));
            float2 a45 = __half22float2(*reinterpret_cast<__half2*>(&ah.z));
            float2 a67 = __half22float2(*reinterpret_cast<__half2*>(&ah.w));
            float as[7] = {a01.x, a01.y, a23.x, a23.y, a45.x, a45.y, a67.x};
#pragma unroll
            for (int k = 0; k < 7; k++)
                z[m][k] = g_x8[(n0 + m) * 8 + k] + as[k];
        }

        float t0[4], t1[4];
#pragma unroll
        for (int m = 0; m < 4; m++) { t0[m] = sba[j]; t1[m] = sba[j + 1]; }
#pragma unroll
        for (int k = 0; k < 7; k++) {
            float2 w = sWa[k * 32 + lane];
#pragma unroll
            for (int m = 0; m < 4; m++) {
                t0[m] += z[m][k] * w.x;
                t1[m] += z[m][k] * w.y;
            }
        }
#pragma unroll
        for (int m = 0; m < 4; m++) { t0[m] = fmaxf(t0[m], 0.f); t1[m] = fmaxf(t1[m], 0.f); }

        // broadcast t via transposed smem tile (replaces 256 SHFL with LDS.128)
        __syncwarp();
        sT[wb + j]     = make_float4(t0[0], t0[1], t0[2], t0[3]);
        sT[wb + j + 1] = make_float4(t1[0], t1[1], t1[2], t1[3]);
        __syncwarp();

        float a0[4], a1[4];
#pragma unroll
        for (int m = 0; m < 4; m++) { a0[m] = sbb[j]; a1[m] = sbb[j + 1]; }
#pragma unroll
        for (int k = 0; k < 64; k++) {
            float2 w = sWb[k * 32 + lane];
            float4 tk = sT[wb + k];
            a0[0] += tk.x * w.x; a1[0] += tk.x * w.y;
            a0[1] += tk.y * w.x; a1[1] += tk.y * w.y;
            a0[2] += tk.z * w.x; a1[2] += tk.z * w.y;
            a0[3] += tk.w * w.x; a1[3] += tk.w * w.y;
        }
#pragma unroll
        for (int m = 0; m < 4; m++) {
            float v0 = fmaxf(a0[m], 0.f);   // outer relu from reference
            float v1 = fmaxf(a1[m], 0.f);
            *reinterpret_cast<__half2*>(g_h1h + (n0 + m) * 64 + j) =
                __floats2half2_rn(v0, v1);
        }
    }
}

// ---------------- layer 2 edge pass (d = 64): 8 lanes per edge --------------
// EXACT R10 version (proven 56.5us): lane owns cols 8l..8l+7; weights in regs;
// pair-unrolled; ONE red.v4.f16x2 per lane per edge. No launch bounds.
#define E2_EPW 8
__global__ void edge2_kernel(const float* __restrict__ ea,
                             const int*   __restrict__ ei,
                             const float* __restrict__ We2,
                             const float* __restrict__ be2) {
    int l    = threadIdx.x & 7;                        // output slice 8l..8l+7
    int grp  = (blockIdx.x * blockDim.x + threadIdx.x) >> 3;
    int base = grp * E2_EPW;

    // per-lane weights: rows 0..3, cols 8l..8l+7 (two float4 per row) + bias
    float4 wa[4], wb[4];
#pragma unroll
    for (int r = 0; r < 4; r++) {
        wa[r] = __ldg(reinterpret_cast<const float4*>(We2 + r * 64) + 2 * l);
        wb[r] = __ldg(reinterpret_cast<const float4*>(We2 + r * 64) + 2 * l + 1);
    }
    float4 ba = __ldg(reinterpret_cast<const float4*>(be2) + 2 * l);
    float4 bc = __ldg(reinterpret_cast<const float4*>(be2) + 2 * l + 1);

#pragma unroll
    for (int i = 0; i < E2_EPW; i += 2) {
        int e0 = base + i;
        int2 s01 = __ldg(reinterpret_cast<const int2*>(ei + e0));
        int2 d01 = __ldg(reinterpret_cast<const int2*>(ei + N_EDGES + e0));
        float4 a0 = __ldg(reinterpret_cast<const float4*>(ea) + e0);
        float4 a1 = __ldg(reinterpret_cast<const float4*>(ea) + e0 + 1);
        uint4 hg0 = __ldg(reinterpret_cast<const uint4*>(g_h1h + s01.x * 64) + l);
        uint4 hg1 = __ldg(reinterpret_cast<const uint4*>(g_h1h + s01.y * 64) + l);

        // edge 0
        {
            float2 h0 = __half22float2(*reinterpret_cast<__half2*>(&hg0.x));
            float2 h1 = __half22float2(*reinterpret_cast<__half2*>(&hg0.y));
            float2 h2 = __half22float2(*reinterpret_cast<__half2*>(&hg0.z));
            float2 h3 = __half22float2(*reinterpret_cast<__half2*>(&hg0.w));
            float m0 = fmaxf(ba.x + a0.x*wa[0].x + a0.y*wa[1].x + a0.z*wa[2].x + a0.w*wa[3].x + h0.x, 0.f);
            float m1 = fmaxf(ba.y + a0.x*wa[0].y + a0.y*wa[1].y + a0.z*wa[2].y + a0.w*wa[3].y + h0.y, 0.f);
            float m2 = fmaxf(ba.z + a0.x*wa[0].z + a0.y*wa[1].z + a0.z*wa[2].z + a0.w*wa[3].z + h1.x, 0.f);
            float m3 = fmaxf(ba.w + a0.x*wa[0].w + a0.y*wa[1].w + a0.z*wa[2].w + a0.w*wa[3].w + h1.y, 0.f);
            float m4 = fmaxf(bc.x + a0.x*wb[0].x + a0.y*wb[1].x + a0.z*wb[2].x + a0.w*wb[3].x + h2.x, 0.f);
            float m5 = fmaxf(bc.y + a0.x*wb[0].y + a0.y*wb[1].y + a0.z*wb[2].y + a0.w*wb[3].y + h2.y, 0.f);
            float m6 = fmaxf(bc.z + a0.x*wb[0].z + a0.y*wb[1].z + a0.z*wb[2].z + a0.w*wb[3].z + h3.x, 0.f);
            float m7 = fmaxf(bc.w + a0.x*wb[0].w + a0.y*wb[1].w + a0.z*wb[2].w + a0.w*wb[3].w + h3.y, 0.f);
            __half2 p0 = __floats2half2_rn(m0, m1);
            __half2 p1 = __floats2half2_rn(m2, m3);
            __half2 p2 = __floats2half2_rn(m4, m5);
            __half2 p3 = __floats2half2_rn(m6, m7);
            __half* p = g_aggr2h + d01.x * 64 + l * 8;
            asm volatile("red.global.add.noftz.v4.f16x2 [%0], {%1, %2, %3, %4};"
                         :: "l"(p),
                            "r"(*reinterpret_cast<unsigned*>(&p0)),
                            "r"(*reinterpret_cast<unsigned*>(&p1)),
                            "r"(*reinterpret_cast<unsigned*>(&p2)),
                            "r"(*reinterpret_cast<unsigned*>(&p3)) : "memory");
        }
        // edge 1
        {
            float2 h0 = __half22float2(*reinterpret_cast<__half2*>(&hg1.x));
            float2 h1 = __half22float2(*reinterpret_cast<__half2*>(&hg1.y));
            float2 h2 = __half22float2(*reinterpret_cast<__half2*>(&hg1.z));
            float2 h3 = __half22float2(*reinterpret_cast<__half2*>(&hg1.w));
            float m0 = fmaxf(ba.x + a1.x*wa[0].x + a1.y*wa[1].x + a1.z*wa[2].x + a1.w*wa[3].x + h0.x, 0.f);
            float m1 = fmaxf(ba.y + a1.x*wa[0].y + a1.y*wa[1].y + a1.z*wa[2].y + a1.w*wa[3].y + h0.y, 0.f);
            float m2 = fmaxf(ba.z + a1.x*wa[0].z + a1.y*wa[1].z + a1.z*wa[2].z + a1.w*wa[3].z + h1.x, 0.f);
            float m3 = fmaxf(ba.w + a1.x*wa[0].w + a1.y*wa[1].w + a1.z*wa[2].w + a1.w*wa[3].w + h1.y, 0.f);
            float m4 = fmaxf(bc.x + a1.x*wb[0].x + a1.y*wb[1].x + a1.z*wb[2].x + a1.w*wb[3].x + h2.x, 0.f);
            float m5 = fmaxf(bc.y + a1.x*wb[0].y + a1.y*wb[1].y + a1.z*wb[2].y + a1.w*wb[3].y + h2.y, 0.f);
            float m6 = fmaxf(bc.z + a1.x*wb[0].z + a1.y*wb[1].z + a1.z*wb[2].z + a1.w*wb[3].z + h3.x, 0.f);
            float m7 = fmaxf(bc.w + a1.x*wb[0].w + a1.y*wb[1].w + a1.z*wb[2].w + a1.w*wb[3].w + h3.y, 0.f);
            __half2 p0 = __floats2half2_rn(m0, m1);
            __half2 p1 = __floats2half2_rn(m2, m3);
            __half2 p2 = __floats2half2_rn(m4, m5);
            __half2 p3 = __floats2half2_rn(m6, m7);
            __half* p = g_aggr2h + d01.y * 64 + l * 8;
            asm volatile("red.global.add.noftz.v4.f16x2 [%0], {%1, %2, %3, %4};"
                         :: "l"(p),
                            "r"(*reinterpret_cast<unsigned*>(&p0)),
                            "r"(*reinterpret_cast<unsigned*>(&p1)),
                            "r"(*reinterpret_cast<unsigned*>(&p2)),
                            "r"(*reinterpret_cast<unsigned*>(&p3)) : "memory");
        }
    }
}

// ---------------- layer 2 node MLP (64->64->64) + pool, 4-node blocked -----
// both layers broadcast via warp-private transposed smem tile (no SHFL)
__global__ void node2pool_kernel(const int*   __restrict__ batch,
                                 const float* __restrict__ W2a,
                                 const float* __restrict__ b2a,
                                 const float* __restrict__ W2b,
                                 const float* __restrict__ b2b) {
    __shared__ float2 sWa[64 * 32];
    __shared__ float2 sWb[64 * 32];
    __shared__ float  sba[64];
    __shared__ float  sbb[64];
    __shared__ float4 sT[8 * 64];     // per-warp 64x4 transposed activations
    for (int i = threadIdx.x; i < 64 * 32; i += blockDim.x) {
        sWa[i] = reinterpret_cast<const float2*>(W2a)[i];
        sWb[i] = reinterpret_cast<const float2*>(W2b)[i];
    }
    if (threadIdx.x < 64) { sba[threadIdx.x] = b2a[threadIdx.x]; sbb[threadIdx.x] = b2b[threadIdx.x]; }
    __syncthreads();

    int warp = (blockIdx.x * blockDim.x + threadIdx.x) >> 5;
    int nw   = (gridDim.x * blockDim.x) >> 5;
    int lane = threadIdx.x & 31;
    int j    = lane * 2;
    int wb   = (threadIdx.x >> 5) * 64;   // warp's smem tile base

    for (int grp = warp; grp < N_GROUPS; grp += nw) {
        int n0 = grp * 4;
        float z0[4], z1[4];
#pragma unroll
        for (int m = 0; m < 4; m++) {
            float2 hv = __half22float2(
                *reinterpret_cast<const __half2*>(g_h1h + (n0 + m) * 64 + j));
            float2 av = __half22float2(
                *reinterpret_cast<const __half2*>(g_aggr2h + (n0 + m) * 64 + j));
            z0[m] = hv.x + av.x;
            z1[m] = hv.y + av.y;
        }

        // broadcast z via transposed smem tile
        __syncwarp();
        sT[wb + j]     = make_float4(z0[0], z0[1], z0[2], z0[3]);
        sT[wb + j + 1] = make_float4(z1[0], z1[1], z1[2], z1[3]);
        __syncwarp();

        float t0[4], t1[4];
#pragma unroll
        for (int m = 0; m < 4; m++) { t0[m] = sba[j]; t1[m] = sba[j + 1]; }
#pragma unroll
        for (int k = 0; k < 64; k++) {
            float2 w = sWa[k * 32 + lane];
            float4 zk = sT[wb + k];
            t0[0] += zk.x * w.x; t1[0] += zk.x * w.y;
            t0[1] += zk.y * w.x; t1[1] += zk.y * w.y;
            t0[2] += zk.z * w.x; t1[2] += zk.z * w.y;
            t0[3] += zk.w * w.x; t1[3] += zk.w * w.y;
        }
#pragma unroll
        for (int m = 0; m < 4; m++) { t0[m] = fmaxf(t0[m], 0.f); t1[m] = fmaxf(t1[m], 0.f); }

        // broadcast t via the same tile (reuse after all z reads complete)
        __syncwarp();
        sT[wb + j]     = make_float4(t0[0], t0[1], t0[2], t0[3]);
        sT[wb + j + 1] = make_float4(t1[0], t1[1], t1[2], t1[3]);
        __syncwarp();

        float a0[4], a1[4];
#pragma unroll
        for (int m = 0; m < 4; m++) { a0[m] = sbb[j]; a1[m] = sbb[j + 1]; }
#pragma unroll
        for (int k = 0; k < 64; k++) {
            float2 w = sWb[k * 32 + lane];
            float4 tk = sT[wb + k];
            a0[0] += tk.x * w.x; a1[0] += tk.x * w.y;
            a0[1] += tk.y * w.x; a1[1] += tk.y * w.y;
            a0[2] += tk.z * w.x; a1[2] += tk.z * w.y;
            a0[3] += tk.w * w.x; a1[3] += tk.w * w.y;
        }
#pragma unroll
        for (int m = 0; m < 4; m++) {
            float v0 = fmaxf(a0[m], 0.f);   // outer relu from reference
            float v1 = fmaxf(a1[m], 0.f);
            int g = batch[n0 + m];
            float* p = g_sums + g * 64 + j;
            asm volatile("red.global.add.v2.f32 [%0], {%1, %2};"
                         :: "l"(p), "f"(v0), "f"(v1) : "memory");
            if (lane == 0) atomicAdd(&g_cnt[g], 1.0f);
        }
    }
}

// ---------------- final FC: pooled[G,64] @ Wfc[64,12] + bfc -----------------
__global__ void fc_kernel(const float* __restrict__ Wfc,
                          const float* __restrict__ bfc,
                          float* __restrict__ out) {
    int i = blockIdx.x * blockDim.x + threadIdx.x;
    if (i >= N_GRAPHS * 12) return;
    int g = i / 12;
    int c = i % 12;
    float inv = 1.0f / fmaxf(g_cnt[g], 1.0f);
    float acc = 0.f;
#pragma unroll
    for (int k = 0; k < 64; k++)
        acc += g_sums[g * 64 + k] * Wfc[k * 12 + c];
    out[i] = bfc[c] + inv * acc;
}

// ---------------- launch ----------------------------------------------------
extern "C" void kernel_launch(void* const* d_in, const int* in_sizes, int n_in,
                              void* d_out, int out_size) {
    const float* x    = (const float*)d_in[0];
    const float* ea   = (const float*)d_in[1];
    const int*   ei   = (const int*)  d_in[2];
    const int*   batch= (const int*)  d_in[3];
    const float* We1  = (const float*)d_in[4];
    const float* be1  = (const float*)d_in[5];
    const float* W1a  = (const float*)d_in[6];
    const float* b1a  = (const float*)d_in[7];
    const float* W1b  = (const float*)d_in[8];
    const float* b1b  = (const float*)d_in[9];
    const float* We2  = (const float*)d_in[10];
    const float* be2  = (const float*)d_in[11];
    const float* W2a  = (const float*)d_in[12];
    const float* b2a  = (const float*)d_in[13];
    const float* W2b  = (const float*)d_in[14];
    const float* b2b  = (const float*)d_in[15];
    const float* Wfc  = (const float*)d_in[16];
    const float* bfc  = (const float*)d_in[17];
    float* out = (float*)d_out;

    zero_kernel<<<(ZSM + 255) / 256, 256>>>(x);
    edge1_kernel<<<1184, 256>>>(ea, ei, We1, be1);
    node1_kernel<<<592, 256>>>(W1a, b1a, W1b, b1b);
    edge2_kernel<<<(N_EDGES / E2_EPW) * 8 / 256, 256>>>(ea, ei, We2, be2);
    node2pool_kernel<<<592, 256>>>(batch, W2a, b2a, W2b, b2b);
    fc_kernel<<<(N_GRAPHS * 12 + 255) / 256, 256>>>(Wfc, bfc, out);
}

// round 15
// speedup vs baseline: 1.2870x; 1.0301x over previous
#include <cuda_runtime.h>
#include <cuda_fp16.h>

#define N_NODES  50000
#define N_EDGES  1600000
#define N_GRAPHS 1000

// ---------------- scratch (device globals; no allocation allowed) ----------
__device__ __align__(16) float  g_x8[N_NODES * 8];      // padded node features (fp32)
__device__ __align__(16) __half g_x8h[N_NODES * 8];     // padded node features (fp16)
__device__ __align__(16) __half g_aggr1h[N_NODES * 8];  // layer1 aggregation (fp16 atomics)
__device__ __align__(16) __half g_h1h[N_NODES * 64];    // layer1 output (fp16 only)
__device__ __align__(16) __half g_aggr2h[N_NODES * 64]; // layer2 aggregation (fp16 atomics)
__device__ __align__(16) float  g_sums[N_GRAPHS * 64];  // pooled sums
__device__ __align__(16) float  g_cnt[N_GRAPHS];        // per-graph node counts

// ---------------- zero scratch + pad x ---------------------------------------
#define ZX  (N_NODES * 2)
#define ZA2 (ZX + N_NODES * 8)
#define ZSM (ZA2 + N_GRAPHS * 16)
__global__ void zero_kernel(const float* __restrict__ x) {
    int i = blockIdx.x * blockDim.x + threadIdx.x;
    if (i < ZX) {
        int node = i >> 1, h = i & 1;
        int base = node * 7 + h * 4;
        float4 v;
        v.x = __ldg(&x[base + 0]);
        v.y = __ldg(&x[base + 1]);
        v.z = __ldg(&x[base + 2]);
        v.w = (h == 0) ? __ldg(&x[base + 3]) : 0.f;   // j=7 pad
        reinterpret_cast<float4*>(g_x8)[i] = v;
        __half2 p0 = __floats2half2_rn(v.x, v.y);
        __half2 p1 = __floats2half2_rn(v.z, v.w);
        uint2 u;
        u.x = *reinterpret_cast<unsigned*>(&p0);
        u.y = *reinterpret_cast<unsigned*>(&p1);
        *reinterpret_cast<uint2*>(reinterpret_cast<char*>(g_x8h) + node * 16 + h * 8) = u;
        if (i < N_NODES)
            reinterpret_cast<uint4*>(g_aggr1h)[i] = make_uint4(0, 0, 0, 0);
    } else if (i < ZA2) {
        reinterpret_cast<uint4*>(g_aggr2h)[i - ZX] = make_uint4(0, 0, 0, 0);
    } else if (i < ZSM) {
        reinterpret_cast<float4*>(g_sums)[i - ZA2] = make_float4(0.f, 0.f, 0.f, 0.f);
    }
    if (i < N_GRAPHS) g_cnt[i] = 0.f;
}

// ---------------- layer 1 edge pass (d = 7): 2 edges/iter, v4.f16x2 red ----
__global__ void edge1_kernel(const float* __restrict__ ea,
                             const int*   __restrict__ ei,
                             const float* __restrict__ We1,
                             const float* __restrict__ be1) {
    float w[4][7], b[7];
#pragma unroll
    for (int i = 0; i < 4; i++)
#pragma unroll
        for (int j = 0; j < 7; j++)
            w[i][j] = __ldg(&We1[i * 7 + j]);
#pragma unroll
    for (int j = 0; j < 7; j++) b[j] = __ldg(&be1[j]);

    int t  = blockIdx.x * blockDim.x + threadIdx.x;
    int nt = gridDim.x * blockDim.x;
    for (int p = t; p < N_EDGES / 2; p += nt) {
        int e0 = p * 2;
        int2 s01 = __ldg(reinterpret_cast<const int2*>(ei) + p);
        int2 d01 = __ldg(reinterpret_cast<const int2*>(ei + N_EDGES) + p);
        float4 a0 = __ldg(reinterpret_cast<const float4*>(ea) + e0);
        float4 a1 = __ldg(reinterpret_cast<const float4*>(ea) + e0 + 1);
        uint4 xh0 = __ldg(reinterpret_cast<const uint4*>(g_x8h) + s01.x);
        uint4 xh1 = __ldg(reinterpret_cast<const uint4*>(g_x8h) + s01.y);

        // edge 0
        {
            float2 x01 = __half22float2(*reinterpret_cast<__half2*>(&xh0.x));
            float2 x23 = __half22float2(*reinterpret_cast<__half2*>(&xh0.y));
            float2 x45 = __half22float2(*reinterpret_cast<__half2*>(&xh0.z));
            float2 x67 = __half22float2(*reinterpret_cast<__half2*>(&xh0.w));
            float xs[8] = {x01.x, x01.y, x23.x, x23.y, x45.x, x45.y, x67.x, 0.f};
            float v[8];
#pragma unroll
            for (int j = 0; j < 7; j++) {
                float m = b[j] + a0.x * w[0][j] + a0.y * w[1][j]
                                + a0.z * w[2][j] + a0.w * w[3][j];
                v[j] = fmaxf(m + xs[j], 0.f);
            }
            v[7] = 0.f;
            __half2 p0 = __floats2half2_rn(v[0], v[1]);
            __half2 p1 = __floats2half2_rn(v[2], v[3]);
            __half2 p2 = __floats2half2_rn(v[4], v[5]);
            __half2 p3 = __floats2half2_rn(v[6], v[7]);
            __half* pp = g_aggr1h + d01.x * 8;
            asm volatile("red.global.add.noftz.v4.f16x2 [%0], {%1, %2, %3, %4};"
                         :: "l"(pp),
                            "r"(*reinterpret_cast<unsigned*>(&p0)),
                            "r"(*reinterpret_cast<unsigned*>(&p1)),
                            "r"(*reinterpret_cast<unsigned*>(&p2)),
                            "r"(*reinterpret_cast<unsigned*>(&p3)) : "memory");
        }
        // edge 1
        {
            float2 x01 = __half22float2(*reinterpret_cast<__half2*>(&xh1.x));
            float2 x23 = __half22float2(*reinterpret_cast<__half2*>(&xh1.y));
            float2 x45 = __half22float2(*reinterpret_cast<__half2*>(&xh1.z));
            float2 x67 = __half22float2(*reinterpret_cast<__half2*>(&xh1.w));
            float xs[8] = {x01.x, x01.y, x23.x, x23.y, x45.x, x45.y, x67.x, 0.f};
            float v[8];
#pragma unroll
            for (int j = 0; j < 7; j++) {
                float m = b[j] + a1.x * w[0][j] + a1.y * w[1][j]
                                + a1.z * w[2][j] + a1.w * w[3][j];
                v[j] = fmaxf(m + xs[j], 0.f);
            }
            v[7] = 0.f;
            __half2 p0 = __floats2half2_rn(v[0], v[1]);
            __half2 p1 = __floats2half2_rn(v[2], v[3]);
            __half2 p2 = __floats2half2_rn(v[4], v[5]);
            __half2 p3 = __floats2half2_rn(v[6], v[7]);
            __half* pp = g_aggr1h + d01.y * 8;
            asm volatile("red.global.add.noftz.v4.f16x2 [%0], {%1, %2, %3, %4};"
                         :: "l"(pp),
                            "r"(*reinterpret_cast<unsigned*>(&p0)),
                            "r"(*reinterpret_cast<unsigned*>(&p1)),
                            "r"(*reinterpret_cast<unsigned*>(&p2)),
                            "r"(*reinterpret_cast<unsigned*>(&p3)) : "memory");
        }
    }
}

// ---------------- layer 1 node MLP: 7 -> 64 -> 64, 8-node + LDS broadcast --
#define N_GROUPS (N_NODES / 8)
__global__ void node1_kernel(const float* __restrict__ W1a,
                             const float* __restrict__ b1a,
                             const float* __restrict__ W1b,
                             const float* __restrict__ b1b) {
    __shared__ float2 sWa[7 * 32];
    __shared__ float2 sWb[64 * 32];
    __shared__ float  sba[64];
    __shared__ float  sbb[64];
    __shared__ float4 sT1[8 * 64];    // per-warp transposed activations, nodes 0-3
    __shared__ float4 sT2[8 * 64];    // nodes 4-7
    for (int i = threadIdx.x; i < 7 * 32; i += blockDim.x)
        sWa[i] = reinterpret_cast<const float2*>(W1a)[i];
    for (int i = threadIdx.x; i < 64 * 32; i += blockDim.x)
        sWb[i] = reinterpret_cast<const float2*>(W1b)[i];
    if (threadIdx.x < 64) { sba[threadIdx.x] = b1a[threadIdx.x]; sbb[threadIdx.x] = b1b[threadIdx.x]; }
    __syncthreads();

    int warp = (blockIdx.x * blockDim.x + threadIdx.x) >> 5;
    int nw   = (gridDim.x * blockDim.x) >> 5;
    int lane = threadIdx.x & 31;
    int j    = lane * 2;
    int wb   = (threadIdx.x >> 5) * 64;

    for (int grp = warp; grp < N_GROUPS; grp += nw) {
        int n0 = grp * 8;
        float z[8][7];
#pragma unroll
        for (int m = 0; m < 8; m++) {
            uint4 ah = *reinterpret_cast<const uint4*>(g_aggr1h + (n0 + m) * 8);
            float2 a01 = __half22float2(*reinterpret_cast<__half2*>(&ah.x));
            float2 a23 = __half22float2(*reinterpret_cast<__half2*>(&ah.y));
            float2 a45 = __half22float2(*reinterpret_cast<__half2*>(&ah.z));
            float2 a67 = __half22float2(*reinterpret_cast<__half2*>(&ah.w));
            float as[7] = {a01.x, a01.y, a23.x, a23.y, a45.x, a45.y, a67.x};
#pragma unroll
            for (int k = 0; k < 7; k++)
                z[m][k] = g_x8[(n0 + m) * 8 + k] + as[k];
        }

        float t0[8], t1[8];
#pragma unroll
        for (int m = 0; m < 8; m++) { t0[m] = sba[j]; t1[m] = sba[j + 1]; }
#pragma unroll
        for (int k = 0; k < 7; k++) {
            float2 w = sWa[k * 32 + lane];
#pragma unroll
            for (int m = 0; m < 8; m++) {
                t0[m] += z[m][k] * w.x;
                t1[m] += z[m][k] * w.y;
            }
        }
#pragma unroll
        for (int m = 0; m < 8; m++) { t0[m] = fmaxf(t0[m], 0.f); t1[m] = fmaxf(t1[m], 0.f); }

        __syncwarp();
        sT1[wb + j]     = make_float4(t0[0], t0[1], t0[2], t0[3]);
        sT1[wb + j + 1] = make_float4(t1[0], t1[1], t1[2], t1[3]);
        sT2[wb + j]     = make_float4(t0[4], t0[5], t0[6], t0[7]);
        sT2[wb + j + 1] = make_float4(t1[4], t1[5], t1[6], t1[7]);
        __syncwarp();

        float a0[8], a1[8];
#pragma unroll
        for (int m = 0; m < 8; m++) { a0[m] = sbb[j]; a1[m] = sbb[j + 1]; }
#pragma unroll
        for (int k = 0; k < 64; k++) {
            float2 w = sWb[k * 32 + lane];
            float4 ta = sT1[wb + k];
            float4 tb = sT2[wb + k];
            a0[0] += ta.x * w.x; a1[0] += ta.x * w.y;
            a0[1] += ta.y * w.x; a1[1] += ta.y * w.y;
            a0[2] += ta.z * w.x; a1[2] += ta.z * w.y;
            a0[3] += ta.w * w.x; a1[3] += ta.w * w.y;
            a0[4] += tb.x * w.x; a1[4] += tb.x * w.y;
            a0[5] += tb.y * w.x; a1[5] += tb.y * w.y;
            a0[6] += tb.z * w.x; a1[6] += tb.z * w.y;
            a0[7] += tb.w * w.x; a1[7] += tb.w * w.y;
        }
#pragma unroll
        for (int m = 0; m < 8; m++) {
            float v0 = fmaxf(a0[m], 0.f);   // outer relu from reference
            float v1 = fmaxf(a1[m], 0.f);
            *reinterpret_cast<__half2*>(g_h1h + (n0 + m) * 64 + j) =
                __floats2half2_rn(v0, v1);
        }
    }
}

// ---------------- layer 2 edge pass (d = 64): 8 lanes per edge --------------
// EXACT R10 version (proven 56.5us). Do not modify.
#define E2_EPW 8
__global__ void edge2_kernel(const float* __restrict__ ea,
                             const int*   __restrict__ ei,
                             const float* __restrict__ We2,
                             const float* __restrict__ be2) {
    int l    = threadIdx.x & 7;                        // output slice 8l..8l+7
    int grp  = (blockIdx.x * blockDim.x + threadIdx.x) >> 3;
    int base = grp * E2_EPW;

    float4 wa[4], wb[4];
#pragma unroll
    for (int r = 0; r < 4; r++) {
        wa[r] = __ldg(reinterpret_cast<const float4*>(We2 + r * 64) + 2 * l);
        wb[r] = __ldg(reinterpret_cast<const float4*>(We2 + r * 64) + 2 * l + 1);
    }
    float4 ba = __ldg(reinterpret_cast<const float4*>(be2) + 2 * l);
    float4 bc = __ldg(reinterpret_cast<const float4*>(be2) + 2 * l + 1);

#pragma unroll
    for (int i = 0; i < E2_EPW; i += 2) {
        int e0 = base + i;
        int2 s01 = __ldg(reinterpret_cast<const int2*>(ei + e0));
        int2 d01 = __ldg(reinterpret_cast<const int2*>(ei + N_EDGES + e0));
        float4 a0 = __ldg(reinterpret_cast<const float4*>(ea) + e0);
        float4 a1 = __ldg(reinterpret_cast<const float4*>(ea) + e0 + 1);
        uint4 hg0 = __ldg(reinterpret_cast<const uint4*>(g_h1h + s01.x * 64) + l);
        uint4 hg1 = __ldg(reinterpret_cast<const uint4*>(g_h1h + s01.y * 64) + l);

        // edge 0
        {
            float2 h0 = __half22float2(*reinterpret_cast<__half2*>(&hg0.x));
            float2 h1 = __half22float2(*reinterpret_cast<__half2*>(&hg0.y));
            float2 h2 = __half22float2(*reinterpret_cast<__half2*>(&hg0.z));
            float2 h3 = __half22float2(*reinterpret_cast<__half2*>(&hg0.w));
            float m0 = fmaxf(ba.x + a0.x*wa[0].x + a0.y*wa[1].x + a0.z*wa[2].x + a0.w*wa[3].x + h0.x, 0.f);
            float m1 = fmaxf(ba.y + a0.x*wa[0].y + a0.y*wa[1].y + a0.z*wa[2].y + a0.w*wa[3].y + h0.y, 0.f);
            float m2 = fmaxf(ba.z + a0.x*wa[0].z + a0.y*wa[1].z + a0.z*wa[2].z + a0.w*wa[3].z + h1.x, 0.f);
            float m3 = fmaxf(ba.w + a0.x*wa[0].w + a0.y*wa[1].w + a0.z*wa[2].w + a0.w*wa[3].w + h1.y, 0.f);
            float m4 = fmaxf(bc.x + a0.x*wb[0].x + a0.y*wb[1].x + a0.z*wb[2].x + a0.w*wb[3].x + h2.x, 0.f);
            float m5 = fmaxf(bc.y + a0.x*wb[0].y + a0.y*wb[1].y + a0.z*wb[2].y + a0.w*wb[3].y + h2.y, 0.f);
            float m6 = fmaxf(bc.z + a0.x*wb[0].z + a0.y*wb[1].z + a0.z*wb[2].z + a0.w*wb[3].z + h3.x, 0.f);
            float m7 = fmaxf(bc.w + a0.x*wb[0].w + a0.y*wb[1].w + a0.z*wb[2].w + a0.w*wb[3].w + h3.y, 0.f);
            __half2 p0 = __floats2half2_rn(m0, m1);
            __half2 p1 = __floats2half2_rn(m2, m3);
            __half2 p2 = __floats2half2_rn(m4, m5);
            __half2 p3 = __floats2half2_rn(m6, m7);
            __half* p = g_aggr2h + d01.x * 64 + l * 8;
            asm volatile("red.global.add.noftz.v4.f16x2 [%0], {%1, %2, %3, %4};"
                         :: "l"(p),
                            "r"(*reinterpret_cast<unsigned*>(&p0)),
                            "r"(*reinterpret_cast<unsigned*>(&p1)),
                            "r"(*reinterpret_cast<unsigned*>(&p2)),
                            "r"(*reinterpret_cast<unsigned*>(&p3)) : "memory");
        }
        // edge 1
        {
            float2 h0 = __half22float2(*reinterpret_cast<__half2*>(&hg1.x));
            float2 h1 = __half22float2(*reinterpret_cast<__half2*>(&hg1.y));
            float2 h2 = __half22float2(*reinterpret_cast<__half2*>(&hg1.z));
            float2 h3 = __half22float2(*reinterpret_cast<__half2*>(&hg1.w));
            float m0 = fmaxf(ba.x + a1.x*wa[0].x + a1.y*wa[1].x + a1.z*wa[2].x + a1.w*wa[3].x + h0.x, 0.f);
            float m1 = fmaxf(ba.y + a1.x*wa[0].y + a1.y*wa[1].y + a1.z*wa[2].y + a1.w*wa[3].y + h0.y, 0.f);
            float m2 = fmaxf(ba.z + a1.x*wa[0].z + a1.y*wa[1].z + a1.z*wa[2].z + a1.w*wa[3].z + h1.x, 0.f);
            float m3 = fmaxf(ba.w + a1.x*wa[0].w + a1.y*wa[1].w + a1.z*wa[2].w + a1.w*wa[3].w + h1.y, 0.f);
            float m4 = fmaxf(bc.x + a1.x*wb[0].x + a1.y*wb[1].x + a1.z*wb[2].x + a1.w*wb[3].x + h2.x, 0.f);
            float m5 = fmaxf(bc.y + a1.x*wb[0].y + a1.y*wb[1].y + a1.z*wb[2].y + a1.w*wb[3].y + h2.y, 0.f);
            float m6 = fmaxf(bc.z + a1.x*wb[0].z + a1.y*wb[1].z + a1.z*wb[2].z + a1.w*wb[3].z + h3.x, 0.f);
            float m7 = fmaxf(bc.w + a1.x*wb[0].w + a1.y*wb[1].w + a1.z*wb[2].w + a1.w*wb[3].w + h3.y, 0.f);
            __half2 p0 = __floats2half2_rn(m0, m1);
            __half2 p1 = __floats2half2_rn(m2, m3);
            __half2 p2 = __floats2half2_rn(m4, m5);
            __half2 p3 = __floats2half2_rn(m6, m7);
            __half* p = g_aggr2h + d01.y * 64 + l * 8;
            asm volatile("red.global.add.noftz.v4.f16x2 [%0], {%1, %2, %3, %4};"
                         :: "l"(p),
                            "r"(*reinterpret_cast<unsigned*>(&p0)),
                            "r"(*reinterpret_cast<unsigned*>(&p1)),
                            "r"(*reinterpret_cast<unsigned*>(&p2)),
                            "r"(*reinterpret_cast<unsigned*>(&p3)) : "memory");
        }
    }
}

// ---------------- layer 2 node MLP (64->64->64) + pool, 8-node + LDS bcast -
__global__ void node2pool_kernel(const int*   __restrict__ batch,
                                 const float* __restrict__ W2a,
                                 const float* __restrict__ b2a,
                                 const float* __restrict__ W2b,
                                 const float* __restrict__ b2b) {
    __shared__ float2 sWa[64 * 32];
    __shared__ float2 sWb[64 * 32];
    __shared__ float  sba[64];
    __shared__ float  sbb[64];
    __shared__ float4 sT1[8 * 64];
    __shared__ float4 sT2[8 * 64];
    for (int i = threadIdx.x; i < 64 * 32; i += blockDim.x) {
        sWa[i] = reinterpret_cast<const float2*>(W2a)[i];
        sWb[i] = reinterpret_cast<const float2*>(W2b)[i];
    }
    if (threadIdx.x < 64) { sba[threadIdx.x] = b2a[threadIdx.x]; sbb[threadIdx.x] = b2b[threadIdx.x]; }
    __syncthreads();

    int warp = (blockIdx.x * blockDim.x + threadIdx.x) >> 5;
    int nw   = (gridDim.x * blockDim.x) >> 5;
    int lane = threadIdx.x & 31;
    int j    = lane * 2;
    int wb   = (threadIdx.x >> 5) * 64;

    for (int grp = warp; grp < N_GROUPS; grp += nw) {
        int n0 = grp * 8;
        float z0[8], z1[8];
#pragma unroll
        for (int m = 0; m < 8; m++) {
            float2 hv = __half22float2(
                *reinterpret_cast<const __half2*>(g_h1h + (n0 + m) * 64 + j));
            float2 av = __half22float2(
                *reinterpret_cast<const __half2*>(g_aggr2h + (n0 + m) * 64 + j));
            z0[m] = hv.x + av.x;
            z1[m] = hv.y + av.y;
        }

        __syncwarp();
        sT1[wb + j]     = make_float4(z0[0], z0[1], z0[2], z0[3]);
        sT1[wb + j + 1] = make_float4(z1[0], z1[1], z1[2], z1[3]);
        sT2[wb + j]     = make_float4(z0[4], z0[5], z0[6], z0[7]);
        sT2[wb + j + 1] = make_float4(z1[4], z1[5], z1[6], z1[7]);
        __syncwarp();

        float t0[8], t1[8];
#pragma unroll
        for (int m = 0; m < 8; m++) { t0[m] = sba[j]; t1[m] = sba[j + 1]; }
#pragma unroll
        for (int k = 0; k < 64; k++) {
            float2 w = sWa[k * 32 + lane];
            float4 za = sT1[wb + k];
            float4 zb = sT2[wb + k];
            t0[0] += za.x * w.x; t1[0] += za.x * w.y;
            t0[1] += za.y * w.x; t1[1] += za.y * w.y;
            t0[2] += za.z * w.x; t1[2] += za.z * w.y;
            t0[3] += za.w * w.x; t1[3] += za.w * w.y;
            t0[4] += zb.x * w.x; t1[4] += zb.x * w.y;
            t0[5] += zb.y * w.x; t1[5] += zb.y * w.y;
            t0[6] += zb.z * w.x; t1[6] += zb.z * w.y;
            t0[7] += zb.w * w.x; t1[7] += zb.w * w.y;
        }
#pragma unroll
        for (int m = 0; m < 8; m++) { t0[m] = fmaxf(t0[m], 0.f); t1[m] = fmaxf(t1[m], 0.f); }

        __syncwarp();
        sT1[wb + j]     = make_float4(t0[0], t0[1], t0[2], t0[3]);
        sT1[wb + j + 1] = make_float4(t1[0], t1[1], t1[2], t1[3]);
        sT2[wb + j]     = make_float4(t0[4], t0[5], t0[6], t0[7]);
        sT2[wb + j + 1] = make_float4(t1[4], t1[5], t1[6], t1[7]);
        __syncwarp();

        float a0[8], a1[8];
#pragma unroll
        for (int m = 0; m < 8; m++) { a0[m] = sbb[j]; a1[m] = sbb[j + 1]; }
#pragma unroll
        for (int k = 0; k < 64; k++) {
            float2 w = sWb[k * 32 + lane];
            float4 ta = sT1[wb + k];
            float4 tb = sT2[wb + k];
            a0[0] += ta.x * w.x; a1[0] += ta.x * w.y;
            a0[1] += ta.y * w.x; a1[1] += ta.y * w.y;
            a0[2] += ta.z * w.x; a1[2] += ta.z * w.y;
            a0[3] += ta.w * w.x; a1[3] += ta.w * w.y;
            a0[4] += tb.x * w.x; a1[4] += tb.x * w.y;
            a0[5] += tb.y * w.x; a1[5] += tb.y * w.y;
            a0[6] += tb.z * w.x; a1[6] += tb.z * w.y;
            a0[7] += tb.w * w.x; a1[7] += tb.w * w.y;
        }
#pragma unroll
        for (int m = 0; m < 8; m++) {
            float v0 = fmaxf(a0[m], 0.f);   // outer relu from reference
            float v1 = fmaxf(a1[m], 0.f);
            int g = batch[n0 + m];
            float* p = g_sums + g * 64 + j;
            asm volatile("red.global.add.v2.f32 [%0], {%1, %2};"
                         :: "l"(p), "f"(v0), "f"(v1) : "memory");
            if (lane == 0) atomicAdd(&g_cnt[g], 1.0f);
        }
    }
}

// ---------------- final FC: pooled[G,64] @ Wfc[64,12] + bfc -----------------
__global__ void fc_kernel(const float* __restrict__ Wfc,
                          const float* __restrict__ bfc,
                          float* __restrict__ out) {
    int i = blockIdx.x * blockDim.x + threadIdx.x;
    if (i >= N_GRAPHS * 12) return;
    int g = i / 12;
    int c = i % 12;
    float inv = 1.0f / fmaxf(g_cnt[g], 1.0f);
    float acc = 0.f;
#pragma unroll
    for (int k = 0; k < 64; k++)
        acc += g_sums[g * 64 + k] * Wfc[k * 12 + c];
    out[i] = bfc[c] + inv * acc;
}

// ---------------- launch ----------------------------------------------------
extern "C" void kernel_launch(void* const* d_in, const int* in_sizes, int n_in,
                              void* d_out, int out_size) {
    const float* x    = (const float*)d_in[0];
    const float* ea   = (const float*)d_in[1];
    const int*   ei   = (const int*)  d_in[2];
    const int*   batch= (const int*)  d_in[3];
    const float* We1  = (const float*)d_in[4];
    const float* be1  = (const float*)d_in[5];
    const float* W1a  = (const float*)d_in[6];
    const float* b1a  = (const float*)d_in[7];
    const float* W1b  = (const float*)d_in[8];
    const float* b1b  = (const float*)d_in[9];
    const float* We2  = (const float*)d_in[10];
    const float* be2  = (const float*)d_in[11];
    const float* W2a  = (const float*)d_in[12];
    const float* b2a  = (const float*)d_in[13];
    const float* W2b  = (const float*)d_in[14];
    const float* b2b  = (const float*)d_in[15];
    const float* Wfc  = (const float*)d_in[16];
    const float* bfc  = (const float*)d_in[17];
    float* out = (float*)d_out;

    zero_kernel<<<(ZSM + 255) / 256, 256>>>(x);
    edge1_kernel<<<1184, 256>>>(ea, ei, We1, be1);
    node1_kernel<<<592, 256>>>(W1a, b1a, W1b, b1b);
    edge2_kernel<<<(N_EDGES / E2_EPW) * 8 / 256, 256>>>(ea, ei, We2, be2);
    node2pool_kernel<<<592, 256>>>(batch, W2a, b2a, W2b, b2b);
    fc_kernel<<<(N_GRAPHS * 12 + 255) / 256, 256>>>(Wfc, bfc, out);
}